// round 1
// baseline (speedup 1.0000x reference)
#include <cuda_runtime.h>
#include <cstdint>

#define NT 32768
#define C  128
#define BATCH 64
#define NSEQ 512
#define H 4
#define DH 32
#define NEDGE 524288
#define EPS 1e-5f

// ---------------- scratch (device globals; no runtime allocation) ----------------
__device__ float g_agg[NT * C];
__device__ float g_cnt[NT];
__device__ float g_hl[NT * C];        // local branch pre-BN
__device__ float g_qkv[NT * 3 * C];
__device__ float g_ao[NT * C];        // attention output (pre out-proj)
__device__ float g_ha[NT * C];        // attn branch pre-BN
__device__ float g_cmb[NT * C];       // bn1(hl) + bn2(ha)
__device__ float g_m1[NT * 2 * C];    // MLP hidden
__device__ float g_t[NT * C];         // pre-BN3
__device__ float g_stats[6 * C];      // sum/sumsq for bn1, bn2, bn3
__device__ float g_coef[6 * C];       // (a, c) for bn1, bn2, bn3

// ---------------- edge scatter: one warp per edge, red.v4 ----------------
__global__ void scatter_kernel(const float* __restrict__ x, const int* __restrict__ ei,
                               float* __restrict__ agg, float* __restrict__ cnt) {
    int warp = (blockIdx.x * blockDim.x + threadIdx.x) >> 5;
    int lane = threadIdx.x & 31;
    if (warp >= NEDGE) return;
    int s = ei[warp];
    int d = ei[NEDGE + warp];
    float4 v = ((const float4*)(x + (size_t)s * C))[lane];
    float* dstp = agg + (size_t)d * C + lane * 4;
    asm volatile("red.global.add.v4.f32 [%0], {%1,%2,%3,%4};"
                 :: "l"(dstp), "f"(v.x), "f"(v.y), "f"(v.z), "f"(v.w) : "memory");
    if (lane == 0) atomicAdd(cnt + d, 1.0f);
}

// ---------------- generic tiled GEMM: out[m,n] = act(A'[m,:]·W[n,:] + bias + resid) ----
// A'[m,k] = A[m,k] / max(rowdiv[m],1) if rowdiv else A[m,k].
// BM=64, BN=64, BK=16, 256 threads, 4x4 microtile.
__global__ __launch_bounds__(256)
void gemm_kernel(const float* __restrict__ A, const float* __restrict__ W,
                 const float* __restrict__ bias, const float* __restrict__ resid,
                 const float* __restrict__ rowdiv, float* __restrict__ out,
                 int K, int Ncols, int relu) {
    __shared__ float As[16][64];
    __shared__ float Ws[16][64];
    int m0 = blockIdx.x * 64;
    int n0 = blockIdx.y * 64;
    int t = threadIdx.x;
    int lr = t >> 2;        // load row 0..63
    int lc = t & 3;         // load float4 col 0..3
    int tx = t & 15;        // compute col group
    int ty = t >> 4;        // compute row group
    float acc[4][4];
#pragma unroll
    for (int i = 0; i < 4; i++)
#pragma unroll
        for (int j = 0; j < 4; j++) acc[i][j] = 0.f;

    for (int k0 = 0; k0 < K; k0 += 16) {
        float4 av = *(const float4*)(A + (size_t)(m0 + lr) * K + k0 + lc * 4);
        if (rowdiv) {
            float ri = 1.f / fmaxf(rowdiv[m0 + lr], 1.f);
            av.x *= ri; av.y *= ri; av.z *= ri; av.w *= ri;
        }
        As[lc * 4 + 0][lr] = av.x; As[lc * 4 + 1][lr] = av.y;
        As[lc * 4 + 2][lr] = av.z; As[lc * 4 + 3][lr] = av.w;
        float4 wv = *(const float4*)(W + (size_t)(n0 + lr) * K + k0 + lc * 4);
        Ws[lc * 4 + 0][lr] = wv.x; Ws[lc * 4 + 1][lr] = wv.y;
        Ws[lc * 4 + 2][lr] = wv.z; Ws[lc * 4 + 3][lr] = wv.w;
        __syncthreads();
#pragma unroll
        for (int k = 0; k < 16; k++) {
            float4 a = *(const float4*)(&As[k][ty << 2]);
            float4 b = *(const float4*)(&Ws[k][tx << 2]);
            acc[0][0] = fmaf(a.x, b.x, acc[0][0]); acc[0][1] = fmaf(a.x, b.y, acc[0][1]);
            acc[0][2] = fmaf(a.x, b.z, acc[0][2]); acc[0][3] = fmaf(a.x, b.w, acc[0][3]);
            acc[1][0] = fmaf(a.y, b.x, acc[1][0]); acc[1][1] = fmaf(a.y, b.y, acc[1][1]);
            acc[1][2] = fmaf(a.y, b.z, acc[1][2]); acc[1][3] = fmaf(a.y, b.w, acc[1][3]);
            acc[2][0] = fmaf(a.z, b.x, acc[2][0]); acc[2][1] = fmaf(a.z, b.y, acc[2][1]);
            acc[2][2] = fmaf(a.z, b.z, acc[2][2]); acc[2][3] = fmaf(a.z, b.w, acc[2][3]);
            acc[3][0] = fmaf(a.w, b.x, acc[3][0]); acc[3][1] = fmaf(a.w, b.y, acc[3][1]);
            acc[3][2] = fmaf(a.w, b.z, acc[3][2]); acc[3][3] = fmaf(a.w, b.w, acc[3][3]);
        }
        __syncthreads();
    }
    int nb = n0 + (tx << 2);
    float4 bv = make_float4(0.f, 0.f, 0.f, 0.f);
    if (bias) bv = *(const float4*)(bias + nb);
#pragma unroll
    for (int i = 0; i < 4; i++) {
        int m = m0 + (ty << 2) + i;
        float4 r = make_float4(acc[i][0] + bv.x, acc[i][1] + bv.y,
                               acc[i][2] + bv.z, acc[i][3] + bv.w);
        if (resid) {
            float4 rv = *(const float4*)(resid + (size_t)m * Ncols + nb);
            r.x += rv.x; r.y += rv.y; r.z += rv.z; r.w += rv.w;
        }
        if (relu) {
            r.x = fmaxf(r.x, 0.f); r.y = fmaxf(r.y, 0.f);
            r.z = fmaxf(r.z, 0.f); r.w = fmaxf(r.w, 0.f);
        }
        *(float4*)(out + (size_t)m * Ncols + nb) = r;
    }
}

// ---------------- attention: one block per (b,h), 512 threads (one q row each) ----
#define ATTN_SMEM (2 * NSEQ * DH * 4)
__global__ __launch_bounds__(512, 1)
void attn_kernel(const float* __restrict__ qkv, float* __restrict__ ao) {
    extern __shared__ float sh[];
    float* Ksh = sh;
    float* Vsh = sh + NSEQ * DH;
    int bh = blockIdx.x;
    int b = bh / H, h = bh % H;
    int t = threadIdx.x;
    size_t base = (size_t)b * NSEQ * 3 * C;

    // load K, V for this head into smem
    for (int idx = t; idx < NSEQ * 8; idx += 512) {
        int row = idx >> 3, j = idx & 7;
        ((float4*)(Ksh + row * DH))[j] =
            ((const float4*)(qkv + base + (size_t)row * 3 * C + C + h * DH))[j];
        ((float4*)(Vsh + row * DH))[j] =
            ((const float4*)(qkv + base + (size_t)row * 3 * C + 2 * C + h * DH))[j];
    }
    // load q row
    float4 q4[8];
    const float4* qp = (const float4*)(qkv + base + (size_t)t * 3 * C + h * DH);
#pragma unroll
    for (int d = 0; d < 8; d++) q4[d] = qp[d];
    __syncthreads();

    const float scale = 0.17677669529663687f;  // 1/sqrt(32)
    float m_run = -1e30f, l_run = 0.f;
    float4 o4[8];
#pragma unroll
    for (int d = 0; d < 8; d++) o4[d] = make_float4(0.f, 0.f, 0.f, 0.f);

    for (int c0 = 0; c0 < NSEQ; c0 += 16) {
        float s[16];
        float cmax = -1e30f;
#pragma unroll
        for (int j = 0; j < 16; j++) {
            const float4* kr = (const float4*)(Ksh + (c0 + j) * DH);
            float acc = 0.f;
#pragma unroll
            for (int d = 0; d < 8; d++) {
                float4 kv = kr[d];
                acc = fmaf(q4[d].x, kv.x, acc); acc = fmaf(q4[d].y, kv.y, acc);
                acc = fmaf(q4[d].z, kv.z, acc); acc = fmaf(q4[d].w, kv.w, acc);
            }
            s[j] = acc * scale;
            cmax = fmaxf(cmax, s[j]);
        }
        float mnew = fmaxf(m_run, cmax);
        float corr = __expf(m_run - mnew);
        l_run *= corr;
#pragma unroll
        for (int d = 0; d < 8; d++) {
            o4[d].x *= corr; o4[d].y *= corr; o4[d].z *= corr; o4[d].w *= corr;
        }
#pragma unroll
        for (int j = 0; j < 16; j++) {
            float p = __expf(s[j] - mnew);
            l_run += p;
            const float4* vr = (const float4*)(Vsh + (c0 + j) * DH);
#pragma unroll
            for (int d = 0; d < 8; d++) {
                float4 vv = vr[d];
                o4[d].x = fmaf(p, vv.x, o4[d].x); o4[d].y = fmaf(p, vv.y, o4[d].y);
                o4[d].z = fmaf(p, vv.z, o4[d].z); o4[d].w = fmaf(p, vv.w, o4[d].w);
            }
        }
        m_run = mnew;
    }
    float linv = 1.f / l_run;
    float4* op = (float4*)(ao + ((size_t)(b * NSEQ + t)) * C + h * DH);
#pragma unroll
    for (int d = 0; d < 8; d++) {
        op[d] = make_float4(o4[d].x * linv, o4[d].y * linv, o4[d].z * linv, o4[d].w * linv);
    }
}

// ---------------- batchnorm stats / coef / apply ----------------
__global__ void bn_stats(const float* __restrict__ src, float* __restrict__ stats) {
    int c = threadIdx.x;                  // 128 channels
    int r0 = blockIdx.x * 64;
    float s = 0.f, ss = 0.f;
    for (int r = 0; r < 64; r++) {
        float v = src[(size_t)(r0 + r) * C + c];
        s += v; ss = fmaf(v, v, ss);
    }
    atomicAdd(&stats[c], s);
    atomicAdd(&stats[C + c], ss);
}

__global__ void bn_coef(const float* __restrict__ stats, const float* __restrict__ g,
                        const float* __restrict__ b, float* __restrict__ coef) {
    int c = threadIdx.x;
    float m = stats[c] * (1.0f / NT);
    float v = stats[C + c] * (1.0f / NT) - m * m;
    float a = g[c] * rsqrtf(v + EPS);
    coef[c] = a;
    coef[C + c] = b[c] - m * a;
}

__global__ void combine_kernel(const float* __restrict__ hl, const float* __restrict__ ha,
                               const float* __restrict__ coef, float* __restrict__ out) {
    int i = blockIdx.x * blockDim.x + threadIdx.x;   // float4 index
    int c4 = (i & 31) * 4;
    float4 a1 = *(const float4*)(coef + c4);
    float4 c1 = *(const float4*)(coef + C + c4);
    float4 a2 = *(const float4*)(coef + 2 * C + c4);
    float4 c2 = *(const float4*)(coef + 3 * C + c4);
    float4 u = ((const float4*)hl)[i];
    float4 v = ((const float4*)ha)[i];
    float4 r;
    r.x = fmaf(u.x, a1.x, c1.x) + fmaf(v.x, a2.x, c2.x);
    r.y = fmaf(u.y, a1.y, c1.y) + fmaf(v.y, a2.y, c2.y);
    r.z = fmaf(u.z, a1.z, c1.z) + fmaf(v.z, a2.z, c2.z);
    r.w = fmaf(u.w, a1.w, c1.w) + fmaf(v.w, a2.w, c2.w);
    ((float4*)out)[i] = r;
}

__global__ void apply_kernel(const float* __restrict__ src, const float* __restrict__ coef,
                             float* __restrict__ out) {
    int i = blockIdx.x * blockDim.x + threadIdx.x;
    int c4 = (i & 31) * 4;
    float4 a = *(const float4*)(coef + c4);
    float4 c = *(const float4*)(coef + C + c4);
    float4 u = ((const float4*)src)[i];
    float4 r;
    r.x = fmaf(u.x, a.x, c.x);
    r.y = fmaf(u.y, a.y, c.y);
    r.z = fmaf(u.z, a.z, c.z);
    r.w = fmaf(u.w, a.w, c.w);
    ((float4*)out)[i] = r;
}

// ---------------- launch ----------------
extern "C" void kernel_launch(void* const* d_in, const int* in_sizes, int n_in,
                              void* d_out, int out_size) {
    const float* x    = (const float*)d_in[0];
    const int*   ei   = (const int*)  d_in[1];
    const float* Wc   = (const float*)d_in[2];
    const float* bc   = (const float*)d_in[3];
    const float* inw  = (const float*)d_in[4];
    const float* inb  = (const float*)d_in[5];
    const float* outw = (const float*)d_in[6];
    const float* outb = (const float*)d_in[7];
    const float* gn1  = (const float*)d_in[8];
    const float* bn1  = (const float*)d_in[9];
    const float* gn2  = (const float*)d_in[10];
    const float* bn2  = (const float*)d_in[11];
    const float* gn3  = (const float*)d_in[12];
    const float* bn3  = (const float*)d_in[13];
    const float* Wm1  = (const float*)d_in[14];
    const float* bm1  = (const float*)d_in[15];
    const float* Wm2  = (const float*)d_in[16];
    const float* bm2  = (const float*)d_in[17];
    float* out = (float*)d_out;

    float *agg, *cnt, *hl, *qkv, *ao, *ha, *cmb, *m1, *tb, *stats, *coef;
    cudaGetSymbolAddress((void**)&agg,   g_agg);
    cudaGetSymbolAddress((void**)&cnt,   g_cnt);
    cudaGetSymbolAddress((void**)&hl,    g_hl);
    cudaGetSymbolAddress((void**)&qkv,   g_qkv);
    cudaGetSymbolAddress((void**)&ao,    g_ao);
    cudaGetSymbolAddress((void**)&ha,    g_ha);
    cudaGetSymbolAddress((void**)&cmb,   g_cmb);
    cudaGetSymbolAddress((void**)&m1,    g_m1);
    cudaGetSymbolAddress((void**)&tb,    g_t);
    cudaGetSymbolAddress((void**)&stats, g_stats);
    cudaGetSymbolAddress((void**)&coef,  g_coef);

    cudaFuncSetAttribute(attn_kernel, cudaFuncAttributeMaxDynamicSharedMemorySize, ATTN_SMEM);

    cudaMemsetAsync(agg, 0, sizeof(float) * NT * C);
    cudaMemsetAsync(cnt, 0, sizeof(float) * NT);
    cudaMemsetAsync(stats, 0, sizeof(float) * 6 * C);

    // local branch
    scatter_kernel<<<NEDGE / 8, 256>>>(x, ei, agg, cnt);
    gemm_kernel<<<dim3(NT / 64, 2), 256>>>(agg, Wc, bc, x, cnt, hl, 128, 128, 0);

    // global branch
    gemm_kernel<<<dim3(NT / 64, 6), 256>>>(x, inw, inb, nullptr, nullptr, qkv, 128, 384, 0);
    attn_kernel<<<BATCH * H, 512, ATTN_SMEM>>>(qkv, ao);
    gemm_kernel<<<dim3(NT / 64, 2), 256>>>(ao, outw, outb, x, nullptr, ha, 128, 128, 0);

    // batchnorm both branches, combine
    bn_stats<<<NT / 64, 128>>>(hl, stats);
    bn_stats<<<NT / 64, 128>>>(ha, stats + 2 * C);
    bn_coef<<<1, 128>>>(stats, gn1, bn1, coef);
    bn_coef<<<1, 128>>>(stats + 2 * C, gn2, bn2, coef + 2 * C);
    combine_kernel<<<NT * C / 4 / 256, 256>>>(hl, ha, coef, cmb);

    // MLP + residual
    gemm_kernel<<<dim3(NT / 64, 4), 256>>>(cmb, Wm1, bm1, nullptr, nullptr, m1, 128, 256, 1);
    gemm_kernel<<<dim3(NT / 64, 2), 256>>>(m1, Wm2, bm2, cmb, nullptr, tb, 256, 128, 0);

    // final BN
    bn_stats<<<NT / 64, 128>>>(tb, stats + 4 * C);
    bn_coef<<<1, 128>>>(stats + 4 * C, gn3, bn3, coef + 4 * C);
    apply_kernel<<<NT * C / 4 / 256, 256>>>(tb, coef + 4 * C, out);
}

// round 4
// speedup vs baseline: 1.2375x; 1.2375x over previous
#include <cuda_runtime.h>
#include <cuda_bf16.h>
#include <cstdint>

#define NT 32768
#define C  128
#define BATCH 64
#define NSEQ 512
#define H 4
#define DH 32
#define NEDGE 524288
#define EPS 1e-5f

// ================= scratch (device globals; no runtime allocation) =================
__device__ float g_agg[NT * C];
__device__ float g_cnt[NT];
__device__ float g_qkv[NT * 3 * C];
__device__ float g_hl[NT * C];
__device__ float g_ha[NT * C];
__device__ float g_cmb[NT * C];
__device__ float g_tb[NT * C];
__device__ float g_stats[6 * C];
__device__ float g_coef[6 * C];
__device__ __nv_bfloat16 g_x_h[NT * C],  g_x_l[NT * C];
__device__ __nv_bfloat16 g_ag_h[NT * C], g_ag_l[NT * C];
__device__ __nv_bfloat16 g_ao_h[NT * C], g_ao_l[NT * C];
__device__ __nv_bfloat16 g_cb_h[NT * C], g_cb_l[NT * C];
__device__ __nv_bfloat16 g_m1_h[NT * 2 * C], g_m1_l[NT * 2 * C];
__device__ __nv_bfloat16 g_wc_h[C * C],     g_wc_l[C * C];
__device__ __nv_bfloat16 g_wi_h[3 * C * C], g_wi_l[3 * C * C];
__device__ __nv_bfloat16 g_wo_h[C * C],     g_wo_l[C * C];
__device__ __nv_bfloat16 g_w1_h[2 * C * C], g_w1_l[2 * C * C];
__device__ __nv_bfloat16 g_w2_h[2 * C * C], g_w2_l[2 * C * C];

// ================= helpers =================
__device__ __forceinline__ uint32_t smem_u32(const void* p) {
    uint32_t a;
    asm("{ .reg .u64 t; cvta.to.shared.u64 t, %1; cvt.u32.u64 %0, t; }" : "=r"(a) : "l"(p));
    return a;
}

__device__ __forceinline__ void split_pair(float a, float b,
                                           __nv_bfloat162& h2, __nv_bfloat162& l2) {
    __nv_bfloat16 ha = __float2bfloat16(a), hb = __float2bfloat16(b);
    h2 = __halves2bfloat162(ha, hb);
    l2 = __halves2bfloat162(__float2bfloat16(a - __bfloat162float(ha)),
                            __float2bfloat16(b - __bfloat162float(hb)));
}

#define LDMX4(r0, r1, r2, r3, a)                                                     \
    asm volatile("ldmatrix.sync.aligned.m8n8.x4.shared.b16 {%0,%1,%2,%3}, [%4];"     \
                 : "=r"(r0), "=r"(r1), "=r"(r2), "=r"(r3) : "r"(a))
#define LDMX2(r0, r1, a)                                                             \
    asm volatile("ldmatrix.sync.aligned.m8n8.x2.shared.b16 {%0,%1}, [%2];"           \
                 : "=r"(r0), "=r"(r1) : "r"(a))
#define MMA16816(cc, aa, b0, b1)                                                     \
    asm volatile("mma.sync.aligned.m16n8k16.row.col.f32.bf16.bf16.f32 "              \
                 "{%0,%1,%2,%3}, {%4,%5,%6,%7}, {%8,%9}, {%0,%1,%2,%3};"             \
                 : "+f"((cc)[0]), "+f"((cc)[1]), "+f"((cc)[2]), "+f"((cc)[3])        \
                 : "r"((aa)[0]), "r"((aa)[1]), "r"((aa)[2]), "r"((aa)[3]),           \
                   "r"(b0), "r"(b1))

// ================= operand conversions =================
__global__ void conv_split(const float* __restrict__ src, __nv_bfloat16* __restrict__ hi,
                           __nv_bfloat16* __restrict__ lo, int n4) {
    int i = blockIdx.x * blockDim.x + threadIdx.x;
    if (i >= n4) return;
    float4 v = ((const float4*)src)[i];
    __nv_bfloat162 h0, l0, h1, l1;
    split_pair(v.x, v.y, h0, l0);
    split_pair(v.z, v.w, h1, l1);
    ((__nv_bfloat162*)hi)[2 * i] = h0; ((__nv_bfloat162*)hi)[2 * i + 1] = h1;
    ((__nv_bfloat162*)lo)[2 * i] = l0; ((__nv_bfloat162*)lo)[2 * i + 1] = l1;
}

__global__ void conv_agg(const float* __restrict__ agg, const float* __restrict__ cnt,
                         __nv_bfloat16* __restrict__ hi, __nv_bfloat16* __restrict__ lo) {
    int i = blockIdx.x * blockDim.x + threadIdx.x;  // float4 index
    float ri = 1.f / fmaxf(cnt[i >> 5], 1.f);
    float4 v = ((const float4*)agg)[i];
    v.x *= ri; v.y *= ri; v.z *= ri; v.w *= ri;
    __nv_bfloat162 h0, l0, h1, l1;
    split_pair(v.x, v.y, h0, l0);
    split_pair(v.z, v.w, h1, l1);
    ((__nv_bfloat162*)hi)[2 * i] = h0; ((__nv_bfloat162*)hi)[2 * i + 1] = h1;
    ((__nv_bfloat162*)lo)[2 * i] = l0; ((__nv_bfloat162*)lo)[2 * i + 1] = l1;
}

// ================= edge scatter =================
__global__ void scatter_kernel(const float* __restrict__ x, const int* __restrict__ ei,
                               float* __restrict__ agg, float* __restrict__ cnt) {
    int warp = (blockIdx.x * blockDim.x + threadIdx.x) >> 5;
    int lane = threadIdx.x & 31;
    if (warp >= NEDGE) return;
    int s = ei[warp];
    int d = ei[NEDGE + warp];
    float4 v = ((const float4*)(x + (size_t)s * C))[lane];
    float* dstp = agg + (size_t)d * C + lane * 4;
    asm volatile("red.global.add.v4.f32 [%0], {%1,%2,%3,%4};"
                 :: "l"(dstp), "f"(v.x), "f"(v.y), "f"(v.z), "f"(v.w) : "memory");
    if (lane == 0) atomicAdd(cnt + d, 1.0f);
}

// ================= mma.sync bf16x3 GEMM: 128x128 tile/CTA =================
// out[m0+r, n0+c] = act( sum_k A[m,k]*W[n,k] + bias[n0+c] (+resid) )
// A: (hi,lo) bf16 [M,K] row-major; W: (hi,lo) bf16 [N,K] row-major. K in {128,256}.
// smem operand tiles: 128 rows x 272B pitch (128 bf16 + 8 pad) each.
#define TPITCH 272
#define TBYTES (128 * TPITCH)           // 34816
#define S_AH 0
#define S_AL TBYTES
#define S_BH (2 * TBYTES)
#define S_BL (3 * TBYTES)
#define GEMM_SMEM (4 * TBYTES)          // 139264; epilogue reuses offset 0
#define EPITCH 132                      // fp32 words per row in epilogue staging

__global__ __launch_bounds__(256, 1)
void gemm_mma(const __nv_bfloat16* __restrict__ Ah, const __nv_bfloat16* __restrict__ Al,
              const __nv_bfloat16* __restrict__ Wh, const __nv_bfloat16* __restrict__ Wl,
              const float* __restrict__ bias, const float* __restrict__ resid,
              float* __restrict__ outf, __nv_bfloat16* __restrict__ outh,
              __nv_bfloat16* __restrict__ outl, float* __restrict__ stats,
              int K, int ostride, int relu) {
    extern __shared__ char smem[];
    uint32_t sb = smem_u32(smem);
    int tid = threadIdx.x, wid = tid >> 5, lane = tid & 31;
    int m0 = blockIdx.x * 128, n0 = blockIdx.y * 128;
    int wm = (wid >> 2) * 64;            // warp row offset in tile
    int wn = (wid & 3) * 32;             // warp col offset in tile

    float acc[4][4][4];
#pragma unroll
    for (int a = 0; a < 4; a++)
#pragma unroll
        for (int b = 0; b < 4; b++)
#pragma unroll
            for (int c = 0; c < 4; c++) acc[a][b][c] = 0.f;

    int nchunk = K >> 7;
    for (int kc = 0; kc < nchunk; kc++) {
        int kb = kc << 7;
        // ---- stage operands into padded smem ----
        {
            const __nv_bfloat16* srcs[4] = { Ah + (size_t)m0 * K, Al + (size_t)m0 * K,
                                             Wh + (size_t)n0 * K, Wl + (size_t)n0 * K };
            const int dsts[4] = { S_AH, S_AL, S_BH, S_BL };
#pragma unroll
            for (int op = 0; op < 4; op++) {
                const __nv_bfloat16* s = srcs[op];
                char* db = smem + dsts[op];
                for (int idx = tid; idx < 2048; idx += 256) {
                    int r = idx >> 4, j = idx & 15;
                    uint4 v = *(const uint4*)(s + (size_t)r * K + kb + j * 8);
                    *(uint4*)(db + r * TPITCH + j * 16) = v;
                }
            }
        }
        __syncthreads();

        // ---- mainloop over k-steps of 16 ----
        uint32_t a_row = (uint32_t)(wm + (lane & 15));
        uint32_t a_coff = (uint32_t)((lane >> 4) * 16);     // bytes
        uint32_t b_row = (uint32_t)(wn + (lane & 7));
        uint32_t b_coff = (uint32_t)(((lane >> 3) & 1) * 16);
#pragma unroll
        for (int ks = 0; ks < 8; ks++) {
            uint32_t kbyte = (uint32_t)(ks * 32);
            uint32_t ah[4][4], al[4][4], bh[4][2], bl[4][2];
#pragma unroll
            for (int mi = 0; mi < 4; mi++) {
                uint32_t ad = sb + S_AH + (a_row + mi * 16) * TPITCH + kbyte + a_coff;
                LDMX4(ah[mi][0], ah[mi][1], ah[mi][2], ah[mi][3], ad);
                LDMX4(al[mi][0], al[mi][1], al[mi][2], al[mi][3], ad + TBYTES);
            }
#pragma unroll
            for (int ni = 0; ni < 4; ni++) {
                uint32_t bd = sb + S_BH + (b_row + ni * 8) * TPITCH + kbyte + b_coff;
                LDMX2(bh[ni][0], bh[ni][1], bd);
                LDMX2(bl[ni][0], bl[ni][1], bd + TBYTES);
            }
#pragma unroll
            for (int mi = 0; mi < 4; mi++)
#pragma unroll
                for (int ni = 0; ni < 4; ni++) {
                    MMA16816(acc[mi][ni], ah[mi], bh[ni][0], bh[ni][1]);
                    MMA16816(acc[mi][ni], ah[mi], bl[ni][0], bl[ni][1]);
                    MMA16816(acc[mi][ni], al[mi], bh[ni][0], bh[ni][1]);
                }
        }
        __syncthreads();
    }

    // ---- stage accumulators to padded fp32 smem ----
    float* ep = (float*)smem;
    {
        int r = (lane >> 2);
        int cfs = 2 * (lane & 3);
#pragma unroll
        for (int mi = 0; mi < 4; mi++)
#pragma unroll
            for (int ni = 0; ni < 4; ni++) {
                int rr = wm + mi * 16 + r;
                int cc = wn + ni * 8 + cfs;
                ep[rr * EPITCH + cc]     = acc[mi][ni][0];
                ep[rr * EPITCH + cc + 1] = acc[mi][ni][1];
                ep[(rr + 8) * EPITCH + cc]     = acc[mi][ni][2];
                ep[(rr + 8) * EPITCH + cc + 1] = acc[mi][ni][3];
            }
    }
    float* sstat = (float*)(smem + 128 * EPITCH * 4);
    if (stats) sstat[tid] = 0.f;
    __syncthreads();

    // ---- coalesced fused epilogue ----
    int ch = (tid & 31) << 2;            // fixed 4 channels within tile
    float4 bv = make_float4(0.f, 0.f, 0.f, 0.f);
    if (bias) bv = *(const float4*)(bias + n0 + ch);
    float s0 = 0, s1 = 0, s2 = 0, s3 = 0, q0 = 0, q1 = 0, q2 = 0, q3 = 0;
#pragma unroll
    for (int it = 0; it < 16; it++) {
        int i = tid + it * 256;
        int row = i >> 5;
        float4 v = *(float4*)(ep + row * EPITCH + ch);
        v.x += bv.x; v.y += bv.y; v.z += bv.z; v.w += bv.w;
        if (resid) {
            float4 rv = *(const float4*)(resid + (size_t)(m0 + row) * C + ch);
            v.x += rv.x; v.y += rv.y; v.z += rv.z; v.w += rv.w;
        }
        if (relu) {
            v.x = fmaxf(v.x, 0.f); v.y = fmaxf(v.y, 0.f);
            v.z = fmaxf(v.z, 0.f); v.w = fmaxf(v.w, 0.f);
        }
        if (stats) {
            s0 += v.x; s1 += v.y; s2 += v.z; s3 += v.w;
            q0 = fmaf(v.x, v.x, q0); q1 = fmaf(v.y, v.y, q1);
            q2 = fmaf(v.z, v.z, q2); q3 = fmaf(v.w, v.w, q3);
        }
        size_t ob = (size_t)(m0 + row) * ostride + n0 + ch;
        if (outf) *(float4*)(outf + ob) = v;
        if (outh) {
            __nv_bfloat162 h0, l0, h1, l1;
            split_pair(v.x, v.y, h0, l0);
            split_pair(v.z, v.w, h1, l1);
            *(__nv_bfloat162*)(outh + ob) = h0; *(__nv_bfloat162*)(outh + ob + 2) = h1;
            *(__nv_bfloat162*)(outl + ob) = l0; *(__nv_bfloat162*)(outl + ob + 2) = l1;
        }
    }
    if (stats) {
        atomicAdd(&sstat[ch + 0], s0); atomicAdd(&sstat[ch + 1], s1);
        atomicAdd(&sstat[ch + 2], s2); atomicAdd(&sstat[ch + 3], s3);
        atomicAdd(&sstat[128 + ch + 0], q0); atomicAdd(&sstat[128 + ch + 1], q1);
        atomicAdd(&sstat[128 + ch + 2], q2); atomicAdd(&sstat[128 + ch + 3], q3);
        __syncthreads();
        atomicAdd(stats + tid, sstat[tid]);
    }
}

// ================= attention (SIMT, online softmax) — emits bf16 hi/lo =================
#define ATTN_SMEM (2 * NSEQ * DH * 4)
__global__ __launch_bounds__(512, 1)
void attn_kernel(const float* __restrict__ qkv, __nv_bfloat16* __restrict__ aoh,
                 __nv_bfloat16* __restrict__ aol) {
    extern __shared__ float sh[];
    float* Ksh = sh;
    float* Vsh = sh + NSEQ * DH;
    int bh = blockIdx.x;
    int b = bh / H, h = bh % H;
    int t = threadIdx.x;
    size_t base = (size_t)b * NSEQ * 3 * C;

    for (int idx = t; idx < NSEQ * 8; idx += 512) {
        int row = idx >> 3, j = idx & 7;
        ((float4*)(Ksh + row * DH))[j] =
            ((const float4*)(qkv + base + (size_t)row * 3 * C + C + h * DH))[j];
        ((float4*)(Vsh + row * DH))[j] =
            ((const float4*)(qkv + base + (size_t)row * 3 * C + 2 * C + h * DH))[j];
    }
    float4 q4[8];
    const float4* qp = (const float4*)(qkv + base + (size_t)t * 3 * C + h * DH);
#pragma unroll
    for (int d = 0; d < 8; d++) q4[d] = qp[d];
    __syncthreads();

    const float scale = 0.17677669529663687f;
    float m_run = -1e30f, l_run = 0.f;
    float4 o4[8];
#pragma unroll
    for (int d = 0; d < 8; d++) o4[d] = make_float4(0.f, 0.f, 0.f, 0.f);

    for (int c0 = 0; c0 < NSEQ; c0 += 16) {
        float s[16];
        float cmax = -1e30f;
#pragma unroll
        for (int j = 0; j < 16; j++) {
            const float4* kr = (const float4*)(Ksh + (c0 + j) * DH);
            float a = 0.f;
#pragma unroll
            for (int d = 0; d < 8; d++) {
                float4 kv = kr[d];
                a = fmaf(q4[d].x, kv.x, a); a = fmaf(q4[d].y, kv.y, a);
                a = fmaf(q4[d].z, kv.z, a); a = fmaf(q4[d].w, kv.w, a);
            }
            s[j] = a * scale;
            cmax = fmaxf(cmax, s[j]);
        }
        float mnew = fmaxf(m_run, cmax);
        float corr = __expf(m_run - mnew);
        l_run *= corr;
#pragma unroll
        for (int d = 0; d < 8; d++) {
            o4[d].x *= corr; o4[d].y *= corr; o4[d].z *= corr; o4[d].w *= corr;
        }
#pragma unroll
        for (int j = 0; j < 16; j++) {
            float p = __expf(s[j] - mnew);
            l_run += p;
            const float4* vr = (const float4*)(Vsh + (c0 + j) * DH);
#pragma unroll
            for (int d = 0; d < 8; d++) {
                float4 vv = vr[d];
                o4[d].x = fmaf(p, vv.x, o4[d].x); o4[d].y = fmaf(p, vv.y, o4[d].y);
                o4[d].z = fmaf(p, vv.z, o4[d].z); o4[d].w = fmaf(p, vv.w, o4[d].w);
            }
        }
        m_run = mnew;
    }
    float linv = 1.f / l_run;
    size_t ob = (size_t)(b * NSEQ + t) * C + h * DH;
#pragma unroll
    for (int d = 0; d < 8; d++) {
        float4 v = make_float4(o4[d].x * linv, o4[d].y * linv, o4[d].z * linv, o4[d].w * linv);
        __nv_bfloat162 h0, l0, h1, l1;
        split_pair(v.x, v.y, h0, l0);
        split_pair(v.z, v.w, h1, l1);
        *(__nv_bfloat162*)(aoh + ob + d * 4)     = h0;
        *(__nv_bfloat162*)(aoh + ob + d * 4 + 2) = h1;
        *(__nv_bfloat162*)(aol + ob + d * 4)     = l0;
        *(__nv_bfloat162*)(aol + ob + d * 4 + 2) = l1;
    }
}

// ================= BN coef / combine / apply =================
__global__ void bn_coef(const float* __restrict__ stats, const float* __restrict__ g,
                        const float* __restrict__ b, float* __restrict__ coef) {
    int c = threadIdx.x;
    float m = stats[c] * (1.0f / NT);
    float v = stats[C + c] * (1.0f / NT) - m * m;
    float a = g[c] * rsqrtf(v + EPS);
    coef[c] = a;
    coef[C + c] = b[c] - m * a;
}

__global__ void combine_kernel(const float* __restrict__ hl, const float* __restrict__ ha,
                               const float* __restrict__ coef, float* __restrict__ out,
                               __nv_bfloat16* __restrict__ oh, __nv_bfloat16* __restrict__ ol) {
    int i = blockIdx.x * blockDim.x + threadIdx.x;
    int c4 = (i & 31) * 4;
    float4 a1 = *(const float4*)(coef + c4);
    float4 c1 = *(const float4*)(coef + C + c4);
    float4 a2 = *(const float4*)(coef + 2 * C + c4);
    float4 c2 = *(const float4*)(coef + 3 * C + c4);
    float4 u = ((const float4*)hl)[i];
    float4 v = ((const float4*)ha)[i];
    float4 r;
    r.x = fmaf(u.x, a1.x, c1.x) + fmaf(v.x, a2.x, c2.x);
    r.y = fmaf(u.y, a1.y, c1.y) + fmaf(v.y, a2.y, c2.y);
    r.z = fmaf(u.z, a1.z, c1.z) + fmaf(v.z, a2.z, c2.z);
    r.w = fmaf(u.w, a1.w, c1.w) + fmaf(v.w, a2.w, c2.w);
    ((float4*)out)[i] = r;
    __nv_bfloat162 h0, l0, h1, l1;
    split_pair(r.x, r.y, h0, l0);
    split_pair(r.z, r.w, h1, l1);
    ((__nv_bfloat162*)oh)[2 * i] = h0; ((__nv_bfloat162*)oh)[2 * i + 1] = h1;
    ((__nv_bfloat162*)ol)[2 * i] = l0; ((__nv_bfloat162*)ol)[2 * i + 1] = l1;
}

__global__ void apply_kernel(const float* __restrict__ src, const float* __restrict__ coef,
                             float* __restrict__ out) {
    int i = blockIdx.x * blockDim.x + threadIdx.x;
    int c4 = (i & 31) * 4;
    float4 a = *(const float4*)(coef + c4);
    float4 c = *(const float4*)(coef + C + c4);
    float4 u = ((const float4*)src)[i];
    float4 r;
    r.x = fmaf(u.x, a.x, c.x);
    r.y = fmaf(u.y, a.y, c.y);
    r.z = fmaf(u.z, a.z, c.z);
    r.w = fmaf(u.w, a.w, c.w);
    ((float4*)out)[i] = r;
}

// ================= launch =================
extern "C" void kernel_launch(void* const* d_in, const int* in_sizes, int n_in,
                              void* d_out, int out_size) {
    const float* x    = (const float*)d_in[0];
    const int*   ei   = (const int*)  d_in[1];
    const float* Wc   = (const float*)d_in[2];
    const float* bc   = (const float*)d_in[3];
    const float* inw  = (const float*)d_in[4];
    const float* inb  = (const float*)d_in[5];
    const float* outw = (const float*)d_in[6];
    const float* outb = (const float*)d_in[7];
    const float* gn1  = (const float*)d_in[8];
    const float* bn1  = (const float*)d_in[9];
    const float* gn2  = (const float*)d_in[10];
    const float* bn2  = (const float*)d_in[11];
    const float* gn3  = (const float*)d_in[12];
    const float* bn3  = (const float*)d_in[13];
    const float* Wm1  = (const float*)d_in[14];
    const float* bm1  = (const float*)d_in[15];
    const float* Wm2  = (const float*)d_in[16];
    const float* bm2  = (const float*)d_in[17];
    float* out = (float*)d_out;

    float *agg, *cnt, *qkv, *hl, *ha, *cmb, *tb, *stats, *coef;
    __nv_bfloat16 *xh, *xl, *agh, *agl, *aoh, *aol, *cbh, *cbl, *m1h, *m1l;
    __nv_bfloat16 *wch, *wcl, *wih, *wil, *woh, *wol, *w1h, *w1l, *w2h, *w2l;
    cudaGetSymbolAddress((void**)&agg, g_agg);   cudaGetSymbolAddress((void**)&cnt, g_cnt);
    cudaGetSymbolAddress((void**)&qkv, g_qkv);   cudaGetSymbolAddress((void**)&hl, g_hl);
    cudaGetSymbolAddress((void**)&ha, g_ha);     cudaGetSymbolAddress((void**)&cmb, g_cmb);
    cudaGetSymbolAddress((void**)&tb, g_tb);     cudaGetSymbolAddress((void**)&stats, g_stats);
    cudaGetSymbolAddress((void**)&coef, g_coef);
    cudaGetSymbolAddress((void**)&xh, g_x_h);    cudaGetSymbolAddress((void**)&xl, g_x_l);
    cudaGetSymbolAddress((void**)&agh, g_ag_h);  cudaGetSymbolAddress((void**)&agl, g_ag_l);
    cudaGetSymbolAddress((void**)&aoh, g_ao_h);  cudaGetSymbolAddress((void**)&aol, g_ao_l);
    cudaGetSymbolAddress((void**)&cbh, g_cb_h);  cudaGetSymbolAddress((void**)&cbl, g_cb_l);
    cudaGetSymbolAddress((void**)&m1h, g_m1_h);  cudaGetSymbolAddress((void**)&m1l, g_m1_l);
    cudaGetSymbolAddress((void**)&wch, g_wc_h);  cudaGetSymbolAddress((void**)&wcl, g_wc_l);
    cudaGetSymbolAddress((void**)&wih, g_wi_h);  cudaGetSymbolAddress((void**)&wil, g_wi_l);
    cudaGetSymbolAddress((void**)&woh, g_wo_h);  cudaGetSymbolAddress((void**)&wol, g_wo_l);
    cudaGetSymbolAddress((void**)&w1h, g_w1_h);  cudaGetSymbolAddress((void**)&w1l, g_w1_l);
    cudaGetSymbolAddress((void**)&w2h, g_w2_h);  cudaGetSymbolAddress((void**)&w2l, g_w2_l);

    cudaFuncSetAttribute(gemm_mma, cudaFuncAttributeMaxDynamicSharedMemorySize, GEMM_SMEM);
    cudaFuncSetAttribute(attn_kernel, cudaFuncAttributeMaxDynamicSharedMemorySize, ATTN_SMEM);

    cudaMemsetAsync(agg, 0, sizeof(float) * NT * C);
    cudaMemsetAsync(cnt, 0, sizeof(float) * NT);
    cudaMemsetAsync(stats, 0, sizeof(float) * 6 * C);

    // operand conversions
    conv_split<<<NT * C / 4 / 256, 256>>>(x, xh, xl, NT * C / 4);
    conv_split<<<16, 256>>>(Wc, wch, wcl, C * C / 4);
    conv_split<<<48, 256>>>(inw, wih, wil, 3 * C * C / 4);
    conv_split<<<16, 256>>>(outw, woh, wol, C * C / 4);
    conv_split<<<32, 256>>>(Wm1, w1h, w1l, 2 * C * C / 4);
    conv_split<<<32, 256>>>(Wm2, w2h, w2l, 2 * C * C / 4);

    // local branch
    scatter_kernel<<<NEDGE / 8, 256>>>(x, ei, agg, cnt);
    conv_agg<<<NT * C / 4 / 256, 256>>>(agg, cnt, agh, agl);
    gemm_mma<<<dim3(NT / 128, 1), 256, GEMM_SMEM>>>(agh, agl, wch, wcl, bc, x,
                                                    hl, nullptr, nullptr, stats, 128, 128, 0);

    // global branch
    gemm_mma<<<dim3(NT / 128, 3), 256, GEMM_SMEM>>>(xh, xl, wih, wil, inb, nullptr,
                                                    qkv, nullptr, nullptr, nullptr, 128, 384, 0);
    attn_kernel<<<BATCH * H, 512, ATTN_SMEM>>>(qkv, aoh, aol);
    gemm_mma<<<dim3(NT / 128, 1), 256, GEMM_SMEM>>>(aoh, aol, woh, wol, outb, x,
                                                    ha, nullptr, nullptr, stats + 2 * C, 128, 128, 0);

    // BN both branches + combine
    bn_coef<<<1, 128>>>(stats, gn1, bn1, coef);
    bn_coef<<<1, 128>>>(stats + 2 * C, gn2, bn2, coef + 2 * C);
    combine_kernel<<<NT * C / 4 / 256, 256>>>(hl, ha, coef, cmb, cbh, cbl);

    // MLP
    gemm_mma<<<dim3(NT / 128, 2), 256, GEMM_SMEM>>>(cbh, cbl, w1h, w1l, bm1, nullptr,
                                                    nullptr, m1h, m1l, nullptr, 128, 256, 1);
    gemm_mma<<<dim3(NT / 128, 1), 256, GEMM_SMEM>>>(m1h, m1l, w2h, w2l, bm2, cmb,
                                                    tb, nullptr, nullptr, stats + 4 * C, 256, 128, 0);

    // final BN
    bn_coef<<<1, 128>>>(stats + 4 * C, gn3, bn3, coef + 4 * C);
    apply_kernel<<<NT * C / 4 / 256, 256>>>(tb, coef + 4 * C, out);
}

// round 5
// speedup vs baseline: 1.9033x; 1.5381x over previous
#include <cuda_runtime.h>
#include <cuda_bf16.h>
#include <cstdint>

#define NT 32768
#define C  128
#define BATCH 64
#define NSEQ 512
#define H 4
#define DH 32
#define NEDGE 524288
#define EPS 1e-5f

// ================= scratch (device globals; no runtime allocation) =================
__device__ float g_agg[NT * C];
__device__ float g_cnt[NT];
__device__ float g_qkv[NT * 3 * C];
__device__ float g_hl[NT * C];
__device__ float g_ha[NT * C];
__device__ float g_cmb[NT * C];
__device__ float g_tb[NT * C];
__device__ float g_stats[6 * C];
__device__ float g_coef[6 * C];
__device__ __nv_bfloat16 g_x_h[NT * C],  g_x_l[NT * C];
__device__ __nv_bfloat16 g_ag_h[NT * C], g_ag_l[NT * C];
__device__ __nv_bfloat16 g_ao_h[NT * C], g_ao_l[NT * C];
__device__ __nv_bfloat16 g_cb_h[NT * C], g_cb_l[NT * C];
__device__ __nv_bfloat16 g_m1_h[NT * 2 * C], g_m1_l[NT * 2 * C];
__device__ __nv_bfloat16 g_wc_h[C * C],     g_wc_l[C * C];
__device__ __nv_bfloat16 g_wi_h[3 * C * C], g_wi_l[3 * C * C];
__device__ __nv_bfloat16 g_wo_h[C * C],     g_wo_l[C * C];
__device__ __nv_bfloat16 g_w1_h[2 * C * C], g_w1_l[2 * C * C];
__device__ __nv_bfloat16 g_w2_h[2 * C * C], g_w2_l[2 * C * C];

// ================= helpers =================
__device__ __forceinline__ uint32_t smem_u32(const void* p) {
    uint32_t a;
    asm("{ .reg .u64 t; cvta.to.shared.u64 t, %1; cvt.u32.u64 %0, t; }" : "=r"(a) : "l"(p));
    return a;
}

__device__ __forceinline__ void split_pair(float a, float b,
                                           __nv_bfloat162& h2, __nv_bfloat162& l2) {
    __nv_bfloat16 ha = __float2bfloat16(a), hb = __float2bfloat16(b);
    h2 = __halves2bfloat162(ha, hb);
    l2 = __halves2bfloat162(__float2bfloat16(a - __bfloat162float(ha)),
                            __float2bfloat16(b - __bfloat162float(hb)));
}
__device__ __forceinline__ uint32_t pack_hi(float a, float b) {
    __nv_bfloat162 h = __halves2bfloat162(__float2bfloat16(a), __float2bfloat16(b));
    return *(uint32_t*)&h;
}
__device__ __forceinline__ uint32_t pack_lo(float a, float b) {
    __nv_bfloat16 ha = __float2bfloat16(a), hb = __float2bfloat16(b);
    __nv_bfloat162 l = __halves2bfloat162(__float2bfloat16(a - __bfloat162float(ha)),
                                          __float2bfloat16(b - __bfloat162float(hb)));
    return *(uint32_t*)&l;
}

#define LDMX4(r0, r1, r2, r3, a)                                                     \
    asm volatile("ldmatrix.sync.aligned.m8n8.x4.shared.b16 {%0,%1,%2,%3}, [%4];"     \
                 : "=r"(r0), "=r"(r1), "=r"(r2), "=r"(r3) : "r"(a))
#define LDMX2(r0, r1, a)                                                             \
    asm volatile("ldmatrix.sync.aligned.m8n8.x2.shared.b16 {%0,%1}, [%2];"           \
                 : "=r"(r0), "=r"(r1) : "r"(a))
#define MMA16816(cc, aa, b0, b1)                                                     \
    asm volatile("mma.sync.aligned.m16n8k16.row.col.f32.bf16.bf16.f32 "              \
                 "{%0,%1,%2,%3}, {%4,%5,%6,%7}, {%8,%9}, {%0,%1,%2,%3};"             \
                 : "+f"((cc)[0]), "+f"((cc)[1]), "+f"((cc)[2]), "+f"((cc)[3])        \
                 : "r"((aa)[0]), "r"((aa)[1]), "r"((aa)[2]), "r"((aa)[3]),           \
                   "r"(b0), "r"(b1))

__device__ __forceinline__ float qmax(float v) {
    v = fmaxf(v, __shfl_xor_sync(0xFFFFFFFFu, v, 1));
    v = fmaxf(v, __shfl_xor_sync(0xFFFFFFFFu, v, 2));
    return v;
}
__device__ __forceinline__ float qsum(float v) {
    v += __shfl_xor_sync(0xFFFFFFFFu, v, 1);
    v += __shfl_xor_sync(0xFFFFFFFFu, v, 2);
    return v;
}

// ================= operand conversions =================
__global__ void conv_split(const float* __restrict__ src, __nv_bfloat16* __restrict__ hi,
                           __nv_bfloat16* __restrict__ lo, int n4) {
    int i = blockIdx.x * blockDim.x + threadIdx.x;
    if (i >= n4) return;
    float4 v = ((const float4*)src)[i];
    __nv_bfloat162 h0, l0, h1, l1;
    split_pair(v.x, v.y, h0, l0);
    split_pair(v.z, v.w, h1, l1);
    ((__nv_bfloat162*)hi)[2 * i] = h0; ((__nv_bfloat162*)hi)[2 * i + 1] = h1;
    ((__nv_bfloat162*)lo)[2 * i] = l0; ((__nv_bfloat162*)lo)[2 * i + 1] = l1;
}

__global__ void conv_agg(const float* __restrict__ agg, const float* __restrict__ cnt,
                         __nv_bfloat16* __restrict__ hi, __nv_bfloat16* __restrict__ lo) {
    int i = blockIdx.x * blockDim.x + threadIdx.x;  // float4 index
    float ri = 1.f / fmaxf(cnt[i >> 5], 1.f);
    float4 v = ((const float4*)agg)[i];
    v.x *= ri; v.y *= ri; v.z *= ri; v.w *= ri;
    __nv_bfloat162 h0, l0, h1, l1;
    split_pair(v.x, v.y, h0, l0);
    split_pair(v.z, v.w, h1, l1);
    ((__nv_bfloat162*)hi)[2 * i] = h0; ((__nv_bfloat162*)hi)[2 * i + 1] = h1;
    ((__nv_bfloat162*)lo)[2 * i] = l0; ((__nv_bfloat162*)lo)[2 * i + 1] = l1;
}

// ================= edge scatter =================
__global__ void scatter_kernel(const float* __restrict__ x, const int* __restrict__ ei,
                               float* __restrict__ agg, float* __restrict__ cnt) {
    int warp = (blockIdx.x * blockDim.x + threadIdx.x) >> 5;
    int lane = threadIdx.x & 31;
    if (warp >= NEDGE) return;
    int s = ei[warp];
    int d = ei[NEDGE + warp];
    float4 v = ((const float4*)(x + (size_t)s * C))[lane];
    float* dstp = agg + (size_t)d * C + lane * 4;
    asm volatile("red.global.add.v4.f32 [%0], {%1,%2,%3,%4};"
                 :: "l"(dstp), "f"(v.x), "f"(v.y), "f"(v.z), "f"(v.w) : "memory");
    if (lane == 0) atomicAdd(cnt + d, 1.0f);
}

// ================= mma.sync bf16x3 GEMM: 128x128 tile/CTA =================
#define TPITCH 272
#define TBYTES (128 * TPITCH)
#define S_AH 0
#define S_AL TBYTES
#define S_BH (2 * TBYTES)
#define S_BL (3 * TBYTES)
#define GEMM_SMEM (4 * TBYTES)
#define EPITCH 132

__global__ __launch_bounds__(256, 1)
void gemm_mma(const __nv_bfloat16* __restrict__ Ah, const __nv_bfloat16* __restrict__ Al,
              const __nv_bfloat16* __restrict__ Wh, const __nv_bfloat16* __restrict__ Wl,
              const float* __restrict__ bias, const float* __restrict__ resid,
              float* __restrict__ outf, __nv_bfloat16* __restrict__ outh,
              __nv_bfloat16* __restrict__ outl, float* __restrict__ stats,
              int K, int ostride, int relu) {
    extern __shared__ char smem[];
    uint32_t sb = smem_u32(smem);
    int tid = threadIdx.x, wid = tid >> 5, lane = tid & 31;
    int m0 = blockIdx.x * 128, n0 = blockIdx.y * 128;
    int wm = (wid >> 2) * 64;
    int wn = (wid & 3) * 32;

    float acc[4][4][4];
#pragma unroll
    for (int a = 0; a < 4; a++)
#pragma unroll
        for (int b = 0; b < 4; b++)
#pragma unroll
            for (int c = 0; c < 4; c++) acc[a][b][c] = 0.f;

    int nchunk = K >> 7;
    for (int kc = 0; kc < nchunk; kc++) {
        int kb = kc << 7;
        {
            const __nv_bfloat16* srcs[4] = { Ah + (size_t)m0 * K, Al + (size_t)m0 * K,
                                             Wh + (size_t)n0 * K, Wl + (size_t)n0 * K };
            const int dsts[4] = { S_AH, S_AL, S_BH, S_BL };
#pragma unroll
            for (int op = 0; op < 4; op++) {
                const __nv_bfloat16* s = srcs[op];
                char* db = smem + dsts[op];
                for (int idx = tid; idx < 2048; idx += 256) {
                    int r = idx >> 4, j = idx & 15;
                    uint4 v = *(const uint4*)(s + (size_t)r * K + kb + j * 8);
                    *(uint4*)(db + r * TPITCH + j * 16) = v;
                }
            }
        }
        __syncthreads();

        uint32_t a_row = (uint32_t)(wm + (lane & 15));
        uint32_t a_coff = (uint32_t)((lane >> 4) * 16);
        uint32_t b_row = (uint32_t)(wn + (lane & 7));
        uint32_t b_coff = (uint32_t)(((lane >> 3) & 1) * 16);
#pragma unroll
        for (int ks = 0; ks < 8; ks++) {
            uint32_t kbyte = (uint32_t)(ks * 32);
            uint32_t ah[4][4], al[4][4], bh[4][2], bl[4][2];
#pragma unroll
            for (int mi = 0; mi < 4; mi++) {
                uint32_t ad = sb + S_AH + (a_row + mi * 16) * TPITCH + kbyte + a_coff;
                LDMX4(ah[mi][0], ah[mi][1], ah[mi][2], ah[mi][3], ad);
                LDMX4(al[mi][0], al[mi][1], al[mi][2], al[mi][3], ad + TBYTES);
            }
#pragma unroll
            for (int ni = 0; ni < 4; ni++) {
                uint32_t bd = sb + S_BH + (b_row + ni * 8) * TPITCH + kbyte + b_coff;
                LDMX2(bh[ni][0], bh[ni][1], bd);
                LDMX2(bl[ni][0], bl[ni][1], bd + TBYTES);
            }
#pragma unroll
            for (int mi = 0; mi < 4; mi++)
#pragma unroll
                for (int ni = 0; ni < 4; ni++) {
                    MMA16816(acc[mi][ni], ah[mi], bh[ni][0], bh[ni][1]);
                    MMA16816(acc[mi][ni], ah[mi], bl[ni][0], bl[ni][1]);
                    MMA16816(acc[mi][ni], al[mi], bh[ni][0], bh[ni][1]);
                }
        }
        __syncthreads();
    }

    float* ep = (float*)smem;
    {
        int r = (lane >> 2);
        int cfs = 2 * (lane & 3);
#pragma unroll
        for (int mi = 0; mi < 4; mi++)
#pragma unroll
            for (int ni = 0; ni < 4; ni++) {
                int rr = wm + mi * 16 + r;
                int cc = wn + ni * 8 + cfs;
                ep[rr * EPITCH + cc]     = acc[mi][ni][0];
                ep[rr * EPITCH + cc + 1] = acc[mi][ni][1];
                ep[(rr + 8) * EPITCH + cc]     = acc[mi][ni][2];
                ep[(rr + 8) * EPITCH + cc + 1] = acc[mi][ni][3];
            }
    }
    float* sstat = (float*)(smem + 128 * EPITCH * 4);
    if (stats) sstat[tid] = 0.f;
    __syncthreads();

    int ch = (tid & 31) << 2;
    float4 bv = make_float4(0.f, 0.f, 0.f, 0.f);
    if (bias) bv = *(const float4*)(bias + n0 + ch);
    float s0 = 0, s1 = 0, s2 = 0, s3 = 0, q0 = 0, q1 = 0, q2 = 0, q3 = 0;
#pragma unroll
    for (int it = 0; it < 16; it++) {
        int i = tid + it * 256;
        int row = i >> 5;
        float4 v = *(float4*)(ep + row * EPITCH + ch);
        v.x += bv.x; v.y += bv.y; v.z += bv.z; v.w += bv.w;
        if (resid) {
            float4 rv = *(const float4*)(resid + (size_t)(m0 + row) * C + ch);
            v.x += rv.x; v.y += rv.y; v.z += rv.z; v.w += rv.w;
        }
        if (relu) {
            v.x = fmaxf(v.x, 0.f); v.y = fmaxf(v.y, 0.f);
            v.z = fmaxf(v.z, 0.f); v.w = fmaxf(v.w, 0.f);
        }
        if (stats) {
            s0 += v.x; s1 += v.y; s2 += v.z; s3 += v.w;
            q0 = fmaf(v.x, v.x, q0); q1 = fmaf(v.y, v.y, q1);
            q2 = fmaf(v.z, v.z, q2); q3 = fmaf(v.w, v.w, q3);
        }
        size_t ob = (size_t)(m0 + row) * ostride + n0 + ch;
        if (outf) *(float4*)(outf + ob) = v;
        if (outh) {
            __nv_bfloat162 h0, l0, h1, l1;
            split_pair(v.x, v.y, h0, l0);
            split_pair(v.z, v.w, h1, l1);
            *(__nv_bfloat162*)(outh + ob) = h0; *(__nv_bfloat162*)(outh + ob + 2) = h1;
            *(__nv_bfloat162*)(outl + ob) = l0; *(__nv_bfloat162*)(outl + ob + 2) = l1;
        }
    }
    if (stats) {
        atomicAdd(&sstat[ch + 0], s0); atomicAdd(&sstat[ch + 1], s1);
        atomicAdd(&sstat[ch + 2], s2); atomicAdd(&sstat[ch + 3], s3);
        atomicAdd(&sstat[128 + ch + 0], q0); atomicAdd(&sstat[128 + ch + 1], q1);
        atomicAdd(&sstat[128 + ch + 2], q2); atomicAdd(&sstat[128 + ch + 3], q3);
        __syncthreads();
        atomicAdd(stats + tid, sstat[tid]);
    }
}

// ================= tensor-core flash attention =================
// One block per (b,h). 256 threads = 8 warps, 64 rows/warp (4 m-tiles of 16).
// smem: K hi/lo [512][40bf16-pitch], V^T hi/lo [32][520bf16-pitch].
#define A_KH 0
#define A_KL 40960
#define A_VH 81920
#define A_VL 115200
#define ATTN_SMEM 148480
#define KP 40     // bf16 pitch of K rows (80B)
#define VP 520    // bf16 pitch of Vt rows (1040B)

__global__ __launch_bounds__(256, 1)
void attn_mma(const float* __restrict__ qkv, __nv_bfloat16* __restrict__ aoh,
              __nv_bfloat16* __restrict__ aol) {
    extern __shared__ char smem[];
    uint32_t sbase = smem_u32(smem);
    __nv_bfloat16* Kh  = (__nv_bfloat16*)(smem + A_KH);
    __nv_bfloat16* Kl  = (__nv_bfloat16*)(smem + A_KL);
    __nv_bfloat16* Vth = (__nv_bfloat16*)(smem + A_VH);
    __nv_bfloat16* Vtl = (__nv_bfloat16*)(smem + A_VL);

    int tid = threadIdx.x, wid = tid >> 5, lane = tid & 31;
    int bh = blockIdx.x, b = bh >> 2, h = bh & 3;
    const float* qb = qkv + (size_t)b * NSEQ * 3 * C + h * DH;

    // ---- stage K (hi/lo) and V^T (hi/lo) ----
    for (int idx = tid; idx < NSEQ * 8; idx += 256) {
        int key = idx >> 3, j = idx & 7;
        const float* rp = qb + (size_t)key * 3 * C;
        float4 kv = *(const float4*)(rp + C + j * 4);
        __nv_bfloat162 h0, l0, h1, l1;
        split_pair(kv.x, kv.y, h0, l0);
        split_pair(kv.z, kv.w, h1, l1);
        *(__nv_bfloat162*)(Kh + key * KP + j * 4)     = h0;
        *(__nv_bfloat162*)(Kh + key * KP + j * 4 + 2) = h1;
        *(__nv_bfloat162*)(Kl + key * KP + j * 4)     = l0;
        *(__nv_bfloat162*)(Kl + key * KP + j * 4 + 2) = l1;
        float4 vv = *(const float4*)(rp + 2 * C + j * 4);
        float vals[4] = { vv.x, vv.y, vv.z, vv.w };
#pragma unroll
        for (int t = 0; t < 4; t++) {
            int d = j * 4 + t;
            __nv_bfloat16 hi = __float2bfloat16(vals[t]);
            Vth[d * VP + key] = hi;
            Vtl[d * VP + key] = __float2bfloat16(vals[t] - __bfloat162float(hi));
        }
    }

    // ---- load Q fragments (scale folded in) ----
    const float scale = 0.17677669529663687f;
    uint32_t Qh[4][2][4], Ql[4][2][4];
    {
        int r0 = wid * 64;
        int qr = lane >> 2, qc = (lane & 3) * 2;
#pragma unroll
        for (int mi = 0; mi < 4; mi++)
#pragma unroll
            for (int ks = 0; ks < 2; ks++)
#pragma unroll
                for (int part = 0; part < 4; part++) {
                    int row = r0 + mi * 16 + qr + (part & 1) * 8;
                    int col = ks * 16 + qc + (part >> 1) * 8;
                    float2 v = *(const float2*)(qb + (size_t)row * 3 * C + col);
                    v.x *= scale; v.y *= scale;
                    Qh[mi][ks][part] = pack_hi(v.x, v.y);
                    Ql[mi][ks][part] = pack_lo(v.x, v.y);
                }
    }
    __syncthreads();

    float mr[8], lr[8];
    float O[4][4][4];
#pragma unroll
    for (int i = 0; i < 8; i++) { mr[i] = -1e30f; lr[i] = 0.f; }
#pragma unroll
    for (int a = 0; a < 4; a++)
#pragma unroll
        for (int bq = 0; bq < 4; bq++)
#pragma unroll
            for (int c = 0; c < 4; c++) O[a][bq][c] = 0.f;

    uint32_t ksel = ((lane >> 3) & 1) * 16;
    uint32_t krow = lane & 7;

    for (int kb = 0; kb < NSEQ; kb += 32) {
        // K fragments for this 32-key chunk
        uint32_t kfh[2][4][2], kfl[2][4][2];
#pragma unroll
        for (int nt = 0; nt < 4; nt++)
#pragma unroll
            for (int ks = 0; ks < 2; ks++) {
                uint32_t ad = sbase + A_KH + (kb + nt * 8 + krow) * 80 + ks * 32 + ksel;
                LDMX2(kfh[ks][nt][0], kfh[ks][nt][1], ad);
                LDMX2(kfl[ks][nt][0], kfl[ks][nt][1], ad + (A_KL - A_KH));
            }

        // scores
        float sc[4][4][4];
#pragma unroll
        for (int mi = 0; mi < 4; mi++)
#pragma unroll
            for (int nt = 0; nt < 4; nt++) {
#pragma unroll
                for (int c = 0; c < 4; c++) sc[mi][nt][c] = 0.f;
#pragma unroll
                for (int ks = 0; ks < 2; ks++) {
                    MMA16816(sc[mi][nt], Qh[mi][ks], kfh[ks][nt][0], kfh[ks][nt][1]);
                    MMA16816(sc[mi][nt], Qh[mi][ks], kfl[ks][nt][0], kfl[ks][nt][1]);
                    MMA16816(sc[mi][nt], Ql[mi][ks], kfh[ks][nt][0], kfh[ks][nt][1]);
                }
            }

        // online softmax + P packing
        uint32_t Ph[4][2][4], Pl[4][2][4];
#pragma unroll
        for (int mi = 0; mi < 4; mi++) {
            float cm0 = -1e30f, cm1 = -1e30f;
#pragma unroll
            for (int nt = 0; nt < 4; nt++) {
                cm0 = fmaxf(cm0, fmaxf(sc[mi][nt][0], sc[mi][nt][1]));
                cm1 = fmaxf(cm1, fmaxf(sc[mi][nt][2], sc[mi][nt][3]));
            }
            cm0 = qmax(cm0); cm1 = qmax(cm1);
            float n0 = fmaxf(mr[2 * mi], cm0), n1 = fmaxf(mr[2 * mi + 1], cm1);
            float c0 = __expf(mr[2 * mi] - n0), c1 = __expf(mr[2 * mi + 1] - n1);
            float s0 = 0.f, s1 = 0.f;
#pragma unroll
            for (int nt = 0; nt < 4; nt++) {
                sc[mi][nt][0] = __expf(sc[mi][nt][0] - n0);
                sc[mi][nt][1] = __expf(sc[mi][nt][1] - n0);
                sc[mi][nt][2] = __expf(sc[mi][nt][2] - n1);
                sc[mi][nt][3] = __expf(sc[mi][nt][3] - n1);
                s0 += sc[mi][nt][0] + sc[mi][nt][1];
                s1 += sc[mi][nt][2] + sc[mi][nt][3];
            }
            s0 = qsum(s0); s1 = qsum(s1);
            lr[2 * mi]     = lr[2 * mi] * c0 + s0;
            lr[2 * mi + 1] = lr[2 * mi + 1] * c1 + s1;
            mr[2 * mi] = n0; mr[2 * mi + 1] = n1;
#pragma unroll
            for (int nd = 0; nd < 4; nd++) {
                O[mi][nd][0] *= c0; O[mi][nd][1] *= c0;
                O[mi][nd][2] *= c1; O[mi][nd][3] *= c1;
            }
#pragma unroll
            for (int kg = 0; kg < 2; kg++) {
                Ph[mi][kg][0] = pack_hi(sc[mi][2 * kg][0],     sc[mi][2 * kg][1]);
                Ph[mi][kg][1] = pack_hi(sc[mi][2 * kg][2],     sc[mi][2 * kg][3]);
                Ph[mi][kg][2] = pack_hi(sc[mi][2 * kg + 1][0], sc[mi][2 * kg + 1][1]);
                Ph[mi][kg][3] = pack_hi(sc[mi][2 * kg + 1][2], sc[mi][2 * kg + 1][3]);
                Pl[mi][kg][0] = pack_lo(sc[mi][2 * kg][0],     sc[mi][2 * kg][1]);
                Pl[mi][kg][1] = pack_lo(sc[mi][2 * kg][2],     sc[mi][2 * kg][3]);
                Pl[mi][kg][2] = pack_lo(sc[mi][2 * kg + 1][0], sc[mi][2 * kg + 1][1]);
                Pl[mi][kg][3] = pack_lo(sc[mi][2 * kg + 1][2], sc[mi][2 * kg + 1][3]);
            }
        }

        // PV accumulate
#pragma unroll
        for (int kg = 0; kg < 2; kg++)
#pragma unroll
            for (int nd = 0; nd < 4; nd++) {
                uint32_t vh0, vh1, vl0, vl1;
                uint32_t ad = sbase + A_VH + (nd * 8 + krow) * 1040 + (kb + kg * 16) * 2 + ksel;
                LDMX2(vh0, vh1, ad);
                LDMX2(vl0, vl1, ad + (A_VL - A_VH));
#pragma unroll
                for (int mi = 0; mi < 4; mi++) {
                    MMA16816(O[mi][nd], Ph[mi][kg], vh0, vh1);
                    MMA16816(O[mi][nd], Ph[mi][kg], vl0, vl1);
                    MMA16816(O[mi][nd], Pl[mi][kg], vh0, vh1);
                }
            }
    }

    // ---- epilogue: normalize, split, store bf16 hi/lo ----
    int r0 = wid * 64;
#pragma unroll
    for (int mi = 0; mi < 4; mi++) {
        float li0 = 1.f / lr[2 * mi], li1 = 1.f / lr[2 * mi + 1];
        int grow = b * NSEQ + r0 + mi * 16 + (lane >> 2);
#pragma unroll
        for (int nd = 0; nd < 4; nd++) {
            int col = h * DH + nd * 8 + (lane & 3) * 2;
            float v0 = O[mi][nd][0] * li0, v1 = O[mi][nd][1] * li0;
            float v2 = O[mi][nd][2] * li1, v3 = O[mi][nd][3] * li1;
            __nv_bfloat162 h0, l0, h1, l1;
            split_pair(v0, v1, h0, l0);
            split_pair(v2, v3, h1, l1);
            *(__nv_bfloat162*)(aoh + (size_t)grow * C + col)       = h0;
            *(__nv_bfloat162*)(aol + (size_t)grow * C + col)       = l0;
            *(__nv_bfloat162*)(aoh + (size_t)(grow + 8) * C + col) = h1;
            *(__nv_bfloat162*)(aol + (size_t)(grow + 8) * C + col) = l1;
        }
    }
}

// ================= BN coef / combine / apply =================
__global__ void bn_coef(const float* __restrict__ stats, const float* __restrict__ g,
                        const float* __restrict__ b, float* __restrict__ coef) {
    int c = threadIdx.x;
    float m = stats[c] * (1.0f / NT);
    float v = stats[C + c] * (1.0f / NT) - m * m;
    float a = g[c] * rsqrtf(v + EPS);
    coef[c] = a;
    coef[C + c] = b[c] - m * a;
}

__global__ void combine_kernel(const float* __restrict__ hl, const float* __restrict__ ha,
                               const float* __restrict__ coef, float* __restrict__ out,
                               __nv_bfloat16* __restrict__ oh, __nv_bfloat16* __restrict__ ol) {
    int i = blockIdx.x * blockDim.x + threadIdx.x;
    int c4 = (i & 31) * 4;
    float4 a1 = *(const float4*)(coef + c4);
    float4 c1 = *(const float4*)(coef + C + c4);
    float4 a2 = *(const float4*)(coef + 2 * C + c4);
    float4 c2 = *(const float4*)(coef + 3 * C + c4);
    float4 u = ((const float4*)hl)[i];
    float4 v = ((const float4*)ha)[i];
    float4 r;
    r.x = fmaf(u.x, a1.x, c1.x) + fmaf(v.x, a2.x, c2.x);
    r.y = fmaf(u.y, a1.y, c1.y) + fmaf(v.y, a2.y, c2.y);
    r.z = fmaf(u.z, a1.z, c1.z) + fmaf(v.z, a2.z, c2.z);
    r.w = fmaf(u.w, a1.w, c1.w) + fmaf(v.w, a2.w, c2.w);
    ((float4*)out)[i] = r;
    __nv_bfloat162 h0, l0, h1, l1;
    split_pair(r.x, r.y, h0, l0);
    split_pair(r.z, r.w, h1, l1);
    ((__nv_bfloat162*)oh)[2 * i] = h0; ((__nv_bfloat162*)oh)[2 * i + 1] = h1;
    ((__nv_bfloat162*)ol)[2 * i] = l0; ((__nv_bfloat162*)ol)[2 * i + 1] = l1;
}

__global__ void apply_kernel(const float* __restrict__ src, const float* __restrict__ coef,
                             float* __restrict__ out) {
    int i = blockIdx.x * blockDim.x + threadIdx.x;
    int c4 = (i & 31) * 4;
    float4 a = *(const float4*)(coef + c4);
    float4 c = *(const float4*)(coef + C + c4);
    float4 u = ((const float4*)src)[i];
    float4 r;
    r.x = fmaf(u.x, a.x, c.x);
    r.y = fmaf(u.y, a.y, c.y);
    r.z = fmaf(u.z, a.z, c.z);
    r.w = fmaf(u.w, a.w, c.w);
    ((float4*)out)[i] = r;
}

// ================= launch =================
extern "C" void kernel_launch(void* const* d_in, const int* in_sizes, int n_in,
                              void* d_out, int out_size) {
    const float* x    = (const float*)d_in[0];
    const int*   ei   = (const int*)  d_in[1];
    const float* Wc   = (const float*)d_in[2];
    const float* bc   = (const float*)d_in[3];
    const float* inw  = (const float*)d_in[4];
    const float* inb  = (const float*)d_in[5];
    const float* outw = (const float*)d_in[6];
    const float* outb = (const float*)d_in[7];
    const float* gn1  = (const float*)d_in[8];
    const float* bn1  = (const float*)d_in[9];
    const float* gn2  = (const float*)d_in[10];
    const float* bn2  = (const float*)d_in[11];
    const float* gn3  = (const float*)d_in[12];
    const float* bn3  = (const float*)d_in[13];
    const float* Wm1  = (const float*)d_in[14];
    const float* bm1  = (const float*)d_in[15];
    const float* Wm2  = (const float*)d_in[16];
    const float* bm2  = (const float*)d_in[17];
    float* out = (float*)d_out;

    float *agg, *cnt, *qkv, *hl, *ha, *cmb, *tb, *stats, *coef;
    __nv_bfloat16 *xh, *xl, *agh, *agl, *aoh, *aol, *cbh, *cbl, *m1h, *m1l;
    __nv_bfloat16 *wch, *wcl, *wih, *wil, *woh, *wol, *w1h, *w1l, *w2h, *w2l;
    cudaGetSymbolAddress((void**)&agg, g_agg);   cudaGetSymbolAddress((void**)&cnt, g_cnt);
    cudaGetSymbolAddress((void**)&qkv, g_qkv);   cudaGetSymbolAddress((void**)&hl, g_hl);
    cudaGetSymbolAddress((void**)&ha, g_ha);     cudaGetSymbolAddress((void**)&cmb, g_cmb);
    cudaGetSymbolAddress((void**)&tb, g_tb);     cudaGetSymbolAddress((void**)&stats, g_stats);
    cudaGetSymbolAddress((void**)&coef, g_coef);
    cudaGetSymbolAddress((void**)&xh, g_x_h);    cudaGetSymbolAddress((void**)&xl, g_x_l);
    cudaGetSymbolAddress((void**)&agh, g_ag_h);  cudaGetSymbolAddress((void**)&agl, g_ag_l);
    cudaGetSymbolAddress((void**)&aoh, g_ao_h);  cudaGetSymbolAddress((void**)&aol, g_ao_l);
    cudaGetSymbolAddress((void**)&cbh, g_cb_h);  cudaGetSymbolAddress((void**)&cbl, g_cb_l);
    cudaGetSymbolAddress((void**)&m1h, g_m1_h);  cudaGetSymbolAddress((void**)&m1l, g_m1_l);
    cudaGetSymbolAddress((void**)&wch, g_wc_h);  cudaGetSymbolAddress((void**)&wcl, g_wc_l);
    cudaGetSymbolAddress((void**)&wih, g_wi_h);  cudaGetSymbolAddress((void**)&wil, g_wi_l);
    cudaGetSymbolAddress((void**)&woh, g_wo_h);  cudaGetSymbolAddress((void**)&wol, g_wo_l);
    cudaGetSymbolAddress((void**)&w1h, g_w1_h);  cudaGetSymbolAddress((void**)&w1l, g_w1_l);
    cudaGetSymbolAddress((void**)&w2h, g_w2_h);  cudaGetSymbolAddress((void**)&w2l, g_w2_l);

    cudaFuncSetAttribute(gemm_mma, cudaFuncAttributeMaxDynamicSharedMemorySize, GEMM_SMEM);
    cudaFuncSetAttribute(attn_mma, cudaFuncAttributeMaxDynamicSharedMemorySize, ATTN_SMEM);

    cudaMemsetAsync(agg, 0, sizeof(float) * NT * C);
    cudaMemsetAsync(cnt, 0, sizeof(float) * NT);
    cudaMemsetAsync(stats, 0, sizeof(float) * 6 * C);

    // operand conversions
    conv_split<<<NT * C / 4 / 256, 256>>>(x, xh, xl, NT * C / 4);
    conv_split<<<16, 256>>>(Wc, wch, wcl, C * C / 4);
    conv_split<<<48, 256>>>(inw, wih, wil, 3 * C * C / 4);
    conv_split<<<16, 256>>>(outw, woh, wol, C * C / 4);
    conv_split<<<32, 256>>>(Wm1, w1h, w1l, 2 * C * C / 4);
    conv_split<<<32, 256>>>(Wm2, w2h, w2l, 2 * C * C / 4);

    // local branch
    scatter_kernel<<<NEDGE / 8, 256>>>(x, ei, agg, cnt);
    conv_agg<<<NT * C / 4 / 256, 256>>>(agg, cnt, agh, agl);
    gemm_mma<<<dim3(NT / 128, 1), 256, GEMM_SMEM>>>(agh, agl, wch, wcl, bc, x,
                                                    hl, nullptr, nullptr, stats, 128, 128, 0);

    // global branch
    gemm_mma<<<dim3(NT / 128, 3), 256, GEMM_SMEM>>>(xh, xl, wih, wil, inb, nullptr,
                                                    qkv, nullptr, nullptr, nullptr, 128, 384, 0);
    attn_mma<<<BATCH * H, 256, ATTN_SMEM>>>(qkv, aoh, aol);
    gemm_mma<<<dim3(NT / 128, 1), 256, GEMM_SMEM>>>(aoh, aol, woh, wol, outb, x,
                                                    ha, nullptr, nullptr, stats + 2 * C, 128, 128, 0);

    // BN both branches + combine
    bn_coef<<<1, 128>>>(stats, gn1, bn1, coef);
    bn_coef<<<1, 128>>>(stats + 2 * C, gn2, bn2, coef + 2 * C);
    combine_kernel<<<NT * C / 4 / 256, 256>>>(hl, ha, coef, cmb, cbh, cbl);

    // MLP
    gemm_mma<<<dim3(NT / 128, 2), 256, GEMM_SMEM>>>(cbh, cbl, w1h, w1l, bm1, nullptr,
                                                    nullptr, m1h, m1l, nullptr, 128, 256, 1);
    gemm_mma<<<dim3(NT / 128, 1), 256, GEMM_SMEM>>>(m1h, m1l, w2h, w2l, bm2, cmb,
                                                    tb, nullptr, nullptr, stats + 4 * C, 256, 128, 0);

    // final BN
    bn_coef<<<1, 128>>>(stats + 4 * C, gn3, bn3, coef + 4 * C);
    apply_kernel<<<NT * C / 4 / 256, 256>>>(tb, coef + 4 * C, out);
}

// round 6
// speedup vs baseline: 1.9937x; 1.0475x over previous
#include <cuda_runtime.h>
#include <cuda_bf16.h>
#include <cstdint>

#define NT 32768
#define C  128
#define BATCH 64
#define NSEQ 512
#define H 4
#define DH 32
#define NEDGE 524288
#define EPS 1e-5f
#define QSCALE 0.17677669529663687f

// ================= scratch =================
__device__ float g_agg[NT * C];
__device__ float g_cnt[NT];
__device__ float g_hl[NT * C];
__device__ float g_ha[NT * C];
__device__ float g_cmb[NT * C];
__device__ float g_tb[NT * C];
__device__ float g_stats[6 * C];
__device__ float g_coef[6 * C];
__device__ float g_inbs[3 * C];
__device__ __nv_bfloat16 g_x_h[NT * C],  g_x_l[NT * C];
__device__ __nv_bfloat16 g_ag_h[NT * C], g_ag_l[NT * C];
__device__ __nv_bfloat16 g_qkvh[NT * 3 * C], g_qkvl[NT * 3 * C];
__device__ __nv_bfloat16 g_ao_h[NT * C], g_ao_l[NT * C];
__device__ __nv_bfloat16 g_m1_h[NT * 2 * C], g_m1_l[NT * 2 * C];
__device__ __nv_bfloat16 g_wc_h[C * C],     g_wc_l[C * C];
__device__ __nv_bfloat16 g_wi_h[3 * C * C], g_wi_l[3 * C * C];
__device__ __nv_bfloat16 g_wo_h[C * C],     g_wo_l[C * C];
__device__ __nv_bfloat16 g_w1_h[2 * C * C], g_w1_l[2 * C * C];
__device__ __nv_bfloat16 g_w2_h[2 * C * C], g_w2_l[2 * C * C];

// ================= helpers =================
__device__ __forceinline__ uint32_t smem_u32(const void* p) {
    uint32_t a;
    asm("{ .reg .u64 t; cvta.to.shared.u64 t, %1; cvt.u32.u64 %0, t; }" : "=r"(a) : "l"(p));
    return a;
}
__device__ __forceinline__ void split_pair(float a, float b,
                                           __nv_bfloat162& h2, __nv_bfloat162& l2) {
    __nv_bfloat16 ha = __float2bfloat16(a), hb = __float2bfloat16(b);
    h2 = __halves2bfloat162(ha, hb);
    l2 = __halves2bfloat162(__float2bfloat16(a - __bfloat162float(ha)),
                            __float2bfloat16(b - __bfloat162float(hb)));
}
__device__ __forceinline__ uint32_t pack_hi(float a, float b) {
    __nv_bfloat162 h = __halves2bfloat162(__float2bfloat16(a), __float2bfloat16(b));
    return *(uint32_t*)&h;
}
__device__ __forceinline__ uint32_t pack_lo(float a, float b) {
    __nv_bfloat16 ha = __float2bfloat16(a), hb = __float2bfloat16(b);
    __nv_bfloat162 l = __halves2bfloat162(__float2bfloat16(a - __bfloat162float(ha)),
                                          __float2bfloat16(b - __bfloat162float(hb)));
    return *(uint32_t*)&l;
}

#define LDMX4(r0, r1, r2, r3, a)                                                     \
    asm volatile("ldmatrix.sync.aligned.m8n8.x4.shared.b16 {%0,%1,%2,%3}, [%4];"     \
                 : "=r"(r0), "=r"(r1), "=r"(r2), "=r"(r3) : "r"(a))
#define LDMX2(r0, r1, a)                                                             \
    asm volatile("ldmatrix.sync.aligned.m8n8.x2.shared.b16 {%0,%1}, [%2];"           \
                 : "=r"(r0), "=r"(r1) : "r"(a))
#define MMA16816(cc, aa, b0, b1)                                                     \
    asm volatile("mma.sync.aligned.m16n8k16.row.col.f32.bf16.bf16.f32 "              \
                 "{%0,%1,%2,%3}, {%4,%5,%6,%7}, {%8,%9}, {%0,%1,%2,%3};"             \
                 : "+f"((cc)[0]), "+f"((cc)[1]), "+f"((cc)[2]), "+f"((cc)[3])        \
                 : "r"((aa)[0]), "r"((aa)[1]), "r"((aa)[2]), "r"((aa)[3]),           \
                   "r"(b0), "r"(b1))

__device__ __forceinline__ float qmax(float v) {
    v = fmaxf(v, __shfl_xor_sync(0xFFFFFFFFu, v, 1));
    v = fmaxf(v, __shfl_xor_sync(0xFFFFFFFFu, v, 2));
    return v;
}
__device__ __forceinline__ float qsum(float v) {
    v += __shfl_xor_sync(0xFFFFFFFFu, v, 1);
    v += __shfl_xor_sync(0xFFFFFFFFu, v, 2);
    return v;
}

// ================= conversions =================
__global__ void conv_split(const float* __restrict__ src, __nv_bfloat16* __restrict__ hi,
                           __nv_bfloat16* __restrict__ lo, int n4) {
    int i = blockIdx.x * blockDim.x + threadIdx.x;
    if (i >= n4) return;
    float4 v = ((const float4*)src)[i];
    __nv_bfloat162 h0, l0, h1, l1;
    split_pair(v.x, v.y, h0, l0);
    split_pair(v.z, v.w, h1, l1);
    ((__nv_bfloat162*)hi)[2 * i] = h0; ((__nv_bfloat162*)hi)[2 * i + 1] = h1;
    ((__nv_bfloat162*)lo)[2 * i] = l0; ((__nv_bfloat162*)lo)[2 * i + 1] = l1;
}

// All weights in one launch. Q rows of in_proj (rows < C) get QSCALE folded in.
// Segments (float4 units): Wc 4096 | inw 12288 | outw 4096 | Wm1 8192 | Wm2 8192 | inb 96
__global__ void conv_weights(const float* __restrict__ Wc, const float* __restrict__ inw,
                             const float* __restrict__ outw, const float* __restrict__ Wm1,
                             const float* __restrict__ Wm2, const float* __restrict__ inb,
                             __nv_bfloat16* __restrict__ wch, __nv_bfloat16* __restrict__ wcl,
                             __nv_bfloat16* __restrict__ wih, __nv_bfloat16* __restrict__ wil,
                             __nv_bfloat16* __restrict__ woh, __nv_bfloat16* __restrict__ wol,
                             __nv_bfloat16* __restrict__ w1h, __nv_bfloat16* __restrict__ w1l,
                             __nv_bfloat16* __restrict__ w2h, __nv_bfloat16* __restrict__ w2l,
                             float* __restrict__ inbs) {
    int i = blockIdx.x * blockDim.x + threadIdx.x;
    if (i >= 36960) return;
    if (i >= 36864) {   // inb -> inbs (scaled for Q block)
        int j = (i - 36864) * 4;
        float4 v = *(const float4*)(inb + j);
        if (j < C) { v.x *= QSCALE; v.y *= QSCALE; v.z *= QSCALE; v.w *= QSCALE; }
        *(float4*)(inbs + j) = v;
        return;
    }
    const float* src; __nv_bfloat16 *hi, *lo; int off; float sc = 1.f;
    if (i < 4096)       { src = Wc;  hi = wch; lo = wcl; off = i; }
    else if (i < 16384) { off = i - 4096;  src = inw; hi = wih; lo = wil;
                          if (off < 4096) sc = QSCALE; }   // Q rows: off/32 < 128
    else if (i < 20480) { off = i - 16384; src = outw; hi = woh; lo = wol; }
    else if (i < 28672) { off = i - 20480; src = Wm1; hi = w1h; lo = w1l; }
    else                { off = i - 28672; src = Wm2; hi = w2h; lo = w2l; }
    float4 v = ((const float4*)src)[off];
    v.x *= sc; v.y *= sc; v.z *= sc; v.w *= sc;
    __nv_bfloat162 h0, l0, h1, l1;
    split_pair(v.x, v.y, h0, l0);
    split_pair(v.z, v.w, h1, l1);
    ((__nv_bfloat162*)hi)[2 * off] = h0; ((__nv_bfloat162*)hi)[2 * off + 1] = h1;
    ((__nv_bfloat162*)lo)[2 * off] = l0; ((__nv_bfloat162*)lo)[2 * off + 1] = l1;
}

__global__ void conv_agg(const float* __restrict__ agg, const float* __restrict__ cnt,
                         __nv_bfloat16* __restrict__ hi, __nv_bfloat16* __restrict__ lo) {
    int i = blockIdx.x * blockDim.x + threadIdx.x;
    float ri = 1.f / fmaxf(cnt[i >> 5], 1.f);
    float4 v = ((const float4*)agg)[i];
    v.x *= ri; v.y *= ri; v.z *= ri; v.w *= ri;
    __nv_bfloat162 h0, l0, h1, l1;
    split_pair(v.x, v.y, h0, l0);
    split_pair(v.z, v.w, h1, l1);
    ((__nv_bfloat162*)hi)[2 * i] = h0; ((__nv_bfloat162*)hi)[2 * i + 1] = h1;
    ((__nv_bfloat162*)lo)[2 * i] = l0; ((__nv_bfloat162*)lo)[2 * i + 1] = l1;
}

// ================= edge scatter =================
__global__ void scatter_kernel(const float* __restrict__ x, const int* __restrict__ ei,
                               float* __restrict__ agg, float* __restrict__ cnt) {
    int warp = (blockIdx.x * blockDim.x + threadIdx.x) >> 5;
    int lane = threadIdx.x & 31;
    if (warp >= NEDGE) return;
    int s = ei[warp];
    int d = ei[NEDGE + warp];
    float4 v = ((const float4*)(x + (size_t)s * C))[lane];
    float* dstp = agg + (size_t)d * C + lane * 4;
    asm volatile("red.global.add.v4.f32 [%0], {%1,%2,%3,%4};"
                 :: "l"(dstp), "f"(v.x), "f"(v.y), "f"(v.z), "f"(v.w) : "memory");
    if (lane == 0) atomicAdd(cnt + d, 1.0f);
}

// ================= mma.sync bf16x3 GEMM: 128x128 tile/CTA =================
// If ccoef != null: A = bn1(fA1)+bn2(fA2) computed in staging (K must be 128),
// cmbout written by blockIdx.y==0.
#define TPITCH 272
#define TBYTES (128 * TPITCH)
#define S_AH 0
#define S_AL TBYTES
#define S_BH (2 * TBYTES)
#define S_BL (3 * TBYTES)
#define GEMM_SMEM (4 * TBYTES)
#define EPITCH 132

__global__ __launch_bounds__(256, 1)
void gemm_mma(const __nv_bfloat16* __restrict__ Ah, const __nv_bfloat16* __restrict__ Al,
              const __nv_bfloat16* __restrict__ Wh, const __nv_bfloat16* __restrict__ Wl,
              const float* __restrict__ bias, const float* __restrict__ resid,
              float* __restrict__ outf, __nv_bfloat16* __restrict__ outh,
              __nv_bfloat16* __restrict__ outl, float* __restrict__ stats,
              const float* __restrict__ fA1, const float* __restrict__ fA2,
              const float* __restrict__ ccoef, float* __restrict__ cmbout,
              int K, int ostride, int relu) {
    extern __shared__ char smem[];
    uint32_t sb = smem_u32(smem);
    int tid = threadIdx.x, wid = tid >> 5, lane = tid & 31;
    int m0 = blockIdx.x * 128, n0 = blockIdx.y * 128;
    int wm = (wid >> 2) * 64;
    int wn = (wid & 3) * 32;

    float acc[4][4][4];
#pragma unroll
    for (int a = 0; a < 4; a++)
#pragma unroll
        for (int b = 0; b < 4; b++)
#pragma unroll
            for (int c = 0; c < 4; c++) acc[a][b][c] = 0.f;

    int nchunk = K >> 7;
    for (int kc = 0; kc < nchunk; kc++) {
        int kb = kc << 7;
        // ---- stage A ----
        if (ccoef) {
            bool wr = (cmbout != nullptr) && (blockIdx.y == 0);
            for (int idx = tid; idx < 2048; idx += 256) {
                int r = idx >> 4, col = (idx & 15) * 8;
                size_t base = (size_t)(m0 + r) * C + col;
                float4 u0 = *(const float4*)(fA1 + base);
                float4 u1 = *(const float4*)(fA1 + base + 4);
                float4 v0 = *(const float4*)(fA2 + base);
                float4 v1 = *(const float4*)(fA2 + base + 4);
                float4 a10 = *(const float4*)(ccoef + col);
                float4 a11 = *(const float4*)(ccoef + col + 4);
                float4 c10 = *(const float4*)(ccoef + C + col);
                float4 c11 = *(const float4*)(ccoef + C + col + 4);
                float4 a20 = *(const float4*)(ccoef + 2 * C + col);
                float4 a21 = *(const float4*)(ccoef + 2 * C + col + 4);
                float4 c20 = *(const float4*)(ccoef + 3 * C + col);
                float4 c21 = *(const float4*)(ccoef + 3 * C + col + 4);
                float4 w0, w1;
                w0.x = fmaf(u0.x, a10.x, c10.x) + fmaf(v0.x, a20.x, c20.x);
                w0.y = fmaf(u0.y, a10.y, c10.y) + fmaf(v0.y, a20.y, c20.y);
                w0.z = fmaf(u0.z, a10.z, c10.z) + fmaf(v0.z, a20.z, c20.z);
                w0.w = fmaf(u0.w, a10.w, c10.w) + fmaf(v0.w, a20.w, c20.w);
                w1.x = fmaf(u1.x, a11.x, c11.x) + fmaf(v1.x, a21.x, c21.x);
                w1.y = fmaf(u1.y, a11.y, c11.y) + fmaf(v1.y, a21.y, c21.y);
                w1.z = fmaf(u1.z, a11.z, c11.z) + fmaf(v1.z, a21.z, c21.z);
                w1.w = fmaf(u1.w, a11.w, c11.w) + fmaf(v1.w, a21.w, c21.w);
                if (wr) {
                    *(float4*)(cmbout + base) = w0;
                    *(float4*)(cmbout + base + 4) = w1;
                }
                __nv_bfloat162 h0, l0, h1, l1, h2, l2, h3, l3;
                split_pair(w0.x, w0.y, h0, l0); split_pair(w0.z, w0.w, h1, l1);
                split_pair(w1.x, w1.y, h2, l2); split_pair(w1.z, w1.w, h3, l3);
                char* dh = smem + S_AH + r * TPITCH + col * 2;
                char* dl = smem + S_AL + r * TPITCH + col * 2;
                *(__nv_bfloat162*)(dh) = h0;      *(__nv_bfloat162*)(dh + 4) = h1;
                *(__nv_bfloat162*)(dh + 8) = h2;  *(__nv_bfloat162*)(dh + 12) = h3;
                *(__nv_bfloat162*)(dl) = l0;      *(__nv_bfloat162*)(dl + 4) = l1;
                *(__nv_bfloat162*)(dl + 8) = l2;  *(__nv_bfloat162*)(dl + 12) = l3;
            }
        } else {
            const __nv_bfloat16* srcs[2] = { Ah + (size_t)m0 * K, Al + (size_t)m0 * K };
            const int dsts[2] = { S_AH, S_AL };
#pragma unroll
            for (int op = 0; op < 2; op++) {
                const __nv_bfloat16* s = srcs[op];
                char* db = smem + dsts[op];
                for (int idx = tid; idx < 2048; idx += 256) {
                    int r = idx >> 4, j = idx & 15;
                    uint4 v = *(const uint4*)(s + (size_t)r * K + kb + j * 8);
                    *(uint4*)(db + r * TPITCH + j * 16) = v;
                }
            }
        }
        // ---- stage W ----
        {
            const __nv_bfloat16* srcs[2] = { Wh + (size_t)n0 * K, Wl + (size_t)n0 * K };
            const int dsts[2] = { S_BH, S_BL };
#pragma unroll
            for (int op = 0; op < 2; op++) {
                const __nv_bfloat16* s = srcs[op];
                char* db = smem + dsts[op];
                for (int idx = tid; idx < 2048; idx += 256) {
                    int r = idx >> 4, j = idx & 15;
                    uint4 v = *(const uint4*)(s + (size_t)r * K + kb + j * 8);
                    *(uint4*)(db + r * TPITCH + j * 16) = v;
                }
            }
        }
        __syncthreads();

        uint32_t a_row = (uint32_t)(wm + (lane & 15));
        uint32_t a_coff = (uint32_t)((lane >> 4) * 16);
        uint32_t b_row = (uint32_t)(wn + (lane & 7));
        uint32_t b_coff = (uint32_t)(((lane >> 3) & 1) * 16);
#pragma unroll
        for (int ks = 0; ks < 8; ks++) {
            uint32_t kbyte = (uint32_t)(ks * 32);
            uint32_t ah[4][4], al[4][4], bh[4][2], bl[4][2];
#pragma unroll
            for (int mi = 0; mi < 4; mi++) {
                uint32_t ad = sb + S_AH + (a_row + mi * 16) * TPITCH + kbyte + a_coff;
                LDMX4(ah[mi][0], ah[mi][1], ah[mi][2], ah[mi][3], ad);
                LDMX4(al[mi][0], al[mi][1], al[mi][2], al[mi][3], ad + TBYTES);
            }
#pragma unroll
            for (int ni = 0; ni < 4; ni++) {
                uint32_t bd = sb + S_BH + (b_row + ni * 8) * TPITCH + kbyte + b_coff;
                LDMX2(bh[ni][0], bh[ni][1], bd);
                LDMX2(bl[ni][0], bl[ni][1], bd + TBYTES);
            }
#pragma unroll
            for (int mi = 0; mi < 4; mi++)
#pragma unroll
                for (int ni = 0; ni < 4; ni++) {
                    MMA16816(acc[mi][ni], ah[mi], bh[ni][0], bh[ni][1]);
                    MMA16816(acc[mi][ni], ah[mi], bl[ni][0], bl[ni][1]);
                    MMA16816(acc[mi][ni], al[mi], bh[ni][0], bh[ni][1]);
                }
        }
        __syncthreads();
    }

    float* ep = (float*)smem;
    {
        int r = (lane >> 2);
        int cfs = 2 * (lane & 3);
#pragma unroll
        for (int mi = 0; mi < 4; mi++)
#pragma unroll
            for (int ni = 0; ni < 4; ni++) {
                int rr = wm + mi * 16 + r;
                int cc = wn + ni * 8 + cfs;
                ep[rr * EPITCH + cc]     = acc[mi][ni][0];
                ep[rr * EPITCH + cc + 1] = acc[mi][ni][1];
                ep[(rr + 8) * EPITCH + cc]     = acc[mi][ni][2];
                ep[(rr + 8) * EPITCH + cc + 1] = acc[mi][ni][3];
            }
    }
    float* sstat = (float*)(smem + 128 * EPITCH * 4);
    if (stats) sstat[tid] = 0.f;
    __syncthreads();

    int ch = (tid & 31) << 2;
    float4 bv = make_float4(0.f, 0.f, 0.f, 0.f);
    if (bias) bv = *(const float4*)(bias + n0 + ch);
    float s0 = 0, s1 = 0, s2 = 0, s3 = 0, q0 = 0, q1 = 0, q2 = 0, q3 = 0;
#pragma unroll
    for (int it = 0; it < 16; it++) {
        int i = tid + it * 256;
        int row = i >> 5;
        float4 v = *(float4*)(ep + row * EPITCH + ch);
        v.x += bv.x; v.y += bv.y; v.z += bv.z; v.w += bv.w;
        if (resid) {
            float4 rv = *(const float4*)(resid + (size_t)(m0 + row) * C + ch);
            v.x += rv.x; v.y += rv.y; v.z += rv.z; v.w += rv.w;
        }
        if (relu) {
            v.x = fmaxf(v.x, 0.f); v.y = fmaxf(v.y, 0.f);
            v.z = fmaxf(v.z, 0.f); v.w = fmaxf(v.w, 0.f);
        }
        if (stats) {
            s0 += v.x; s1 += v.y; s2 += v.z; s3 += v.w;
            q0 = fmaf(v.x, v.x, q0); q1 = fmaf(v.y, v.y, q1);
            q2 = fmaf(v.z, v.z, q2); q3 = fmaf(v.w, v.w, q3);
        }
        size_t ob = (size_t)(m0 + row) * ostride + n0 + ch;
        if (outf) *(float4*)(outf + ob) = v;
        if (outh) {
            __nv_bfloat162 h0, l0, h1, l1;
            split_pair(v.x, v.y, h0, l0);
            split_pair(v.z, v.w, h1, l1);
            *(__nv_bfloat162*)(outh + ob) = h0; *(__nv_bfloat162*)(outh + ob + 2) = h1;
            *(__nv_bfloat162*)(outl + ob) = l0; *(__nv_bfloat162*)(outl + ob + 2) = l1;
        }
    }
    if (stats) {
        atomicAdd(&sstat[ch + 0], s0); atomicAdd(&sstat[ch + 1], s1);
        atomicAdd(&sstat[ch + 2], s2); atomicAdd(&sstat[ch + 3], s3);
        atomicAdd(&sstat[128 + ch + 0], q0); atomicAdd(&sstat[128 + ch + 1], q1);
        atomicAdd(&sstat[128 + ch + 2], q2); atomicAdd(&sstat[128 + ch + 3], q3);
        __syncthreads();
        atomicAdd(stats + tid, sstat[tid]);
    }
}

// ================= tensor-core flash attention (bf16 hi/lo qkv input) =============
// One block per (b,h), 256 threads, 64 q-rows/warp. Scale pre-folded into Q proj.
// smem: K hi [512][40], K lo [512][40], V^T hi [32][520].
#define A_KH 0
#define A_KL 40960
#define A_VH 81920
#define ATTN_SMEM 115200
#define KP 40
#define VP 520

__global__ __launch_bounds__(256, 1)
void attn_mma(const __nv_bfloat16* __restrict__ qkvh, const __nv_bfloat16* __restrict__ qkvl,
              __nv_bfloat16* __restrict__ aoh, __nv_bfloat16* __restrict__ aol) {
    extern __shared__ char smem[];
    uint32_t sbase = smem_u32(smem);
    int tid = threadIdx.x, wid = tid >> 5, lane = tid & 31;
    int bh = blockIdx.x, b = bh >> 2, h = bh & 3;
    size_t base = (size_t)b * NSEQ * 3 * C;
    const __nv_bfloat16* kh = qkvh + base + C + h * DH;
    const __nv_bfloat16* kl = qkvl + base + C + h * DH;
    const __nv_bfloat16* vh = qkvh + base + 2 * C + h * DH;
    const __nv_bfloat16* qh = qkvh + base + h * DH;
    const __nv_bfloat16* ql = qkvl + base + h * DH;

    // stage K hi/lo (pure copies)
    for (int idx = tid; idx < NSEQ * 4; idx += 256) {
        int key = idx >> 2, j = idx & 3;
        *(uint4*)(smem + A_KH + key * 80 + j * 16) = *(const uint4*)(kh + (size_t)key * 384 + j * 8);
        *(uint4*)(smem + A_KL + key * 80 + j * 16) = *(const uint4*)(kl + (size_t)key * 384 + j * 8);
    }
    // stage V^T hi (transpose)
    for (int idx = tid; idx < NSEQ * 16; idx += 256) {
        int key = idx >> 4, d2 = idx & 15;
        __nv_bfloat162 v = *(const __nv_bfloat162*)(vh + (size_t)key * 384 + d2 * 2);
        __nv_bfloat16* Vt = (__nv_bfloat16*)(smem + A_VH);
        Vt[(2 * d2) * VP + key]     = __low2bfloat16(v);
        Vt[(2 * d2 + 1) * VP + key] = __high2bfloat16(v);
    }

    // Q fragments (bf16 hi/lo direct loads)
    uint32_t Qh[4][2][4], Ql[4][2][4];
    {
        int r0 = wid * 64;
        int qr = lane >> 2, qc = (lane & 3) * 2;
#pragma unroll
        for (int mi = 0; mi < 4; mi++)
#pragma unroll
            for (int ks = 0; ks < 2; ks++)
#pragma unroll
                for (int part = 0; part < 4; part++) {
                    int row = r0 + mi * 16 + qr + (part & 1) * 8;
                    int col = ks * 16 + qc + (part >> 1) * 8;
                    Qh[mi][ks][part] = *(const uint32_t*)(qh + (size_t)row * 384 + col);
                    Ql[mi][ks][part] = *(const uint32_t*)(ql + (size_t)row * 384 + col);
                }
    }
    __syncthreads();

    float mr[8], lr[8];
    float O[4][4][4];
#pragma unroll
    for (int i = 0; i < 8; i++) { mr[i] = -1e30f; lr[i] = 0.f; }
#pragma unroll
    for (int a = 0; a < 4; a++)
#pragma unroll
        for (int bq = 0; bq < 4; bq++)
#pragma unroll
            for (int c = 0; c < 4; c++) O[a][bq][c] = 0.f;

    uint32_t ksel = ((lane >> 3) & 1) * 16;
    uint32_t krow = lane & 7;

    for (int kb = 0; kb < NSEQ; kb += 32) {
        uint32_t kfh[2][4][2], kfl[2][4][2];
#pragma unroll
        for (int nt = 0; nt < 4; nt++)
#pragma unroll
            for (int ks = 0; ks < 2; ks++) {
                uint32_t ad = sbase + A_KH + (kb + nt * 8 + krow) * 80 + ks * 32 + ksel;
                LDMX2(kfh[ks][nt][0], kfh[ks][nt][1], ad);
                LDMX2(kfl[ks][nt][0], kfl[ks][nt][1], ad + (A_KL - A_KH));
            }

        float sc[4][4][4];
#pragma unroll
        for (int mi = 0; mi < 4; mi++)
#pragma unroll
            for (int nt = 0; nt < 4; nt++) {
#pragma unroll
                for (int c = 0; c < 4; c++) sc[mi][nt][c] = 0.f;
#pragma unroll
                for (int ks = 0; ks < 2; ks++) {
                    MMA16816(sc[mi][nt], Qh[mi][ks], kfh[ks][nt][0], kfh[ks][nt][1]);
                    MMA16816(sc[mi][nt], Qh[mi][ks], kfl[ks][nt][0], kfl[ks][nt][1]);
                    MMA16816(sc[mi][nt], Ql[mi][ks], kfh[ks][nt][0], kfh[ks][nt][1]);
                }
            }

        uint32_t Ph[4][2][4], Pl[4][2][4];
#pragma unroll
        for (int mi = 0; mi < 4; mi++) {
            float cm0 = -1e30f, cm1 = -1e30f;
#pragma unroll
            for (int nt = 0; nt < 4; nt++) {
                cm0 = fmaxf(cm0, fmaxf(sc[mi][nt][0], sc[mi][nt][1]));
                cm1 = fmaxf(cm1, fmaxf(sc[mi][nt][2], sc[mi][nt][3]));
            }
            cm0 = qmax(cm0); cm1 = qmax(cm1);
            float n0 = fmaxf(mr[2 * mi], cm0), n1 = fmaxf(mr[2 * mi + 1], cm1);
            float c0 = __expf(mr[2 * mi] - n0), c1 = __expf(mr[2 * mi + 1] - n1);
            float s0 = 0.f, s1 = 0.f;
#pragma unroll
            for (int nt = 0; nt < 4; nt++) {
                sc[mi][nt][0] = __expf(sc[mi][nt][0] - n0);
                sc[mi][nt][1] = __expf(sc[mi][nt][1] - n0);
                sc[mi][nt][2] = __expf(sc[mi][nt][2] - n1);
                sc[mi][nt][3] = __expf(sc[mi][nt][3] - n1);
                s0 += sc[mi][nt][0] + sc[mi][nt][1];
                s1 += sc[mi][nt][2] + sc[mi][nt][3];
            }
            s0 = qsum(s0); s1 = qsum(s1);
            lr[2 * mi]     = lr[2 * mi] * c0 + s0;
            lr[2 * mi + 1] = lr[2 * mi + 1] * c1 + s1;
            mr[2 * mi] = n0; mr[2 * mi + 1] = n1;
#pragma unroll
            for (int nd = 0; nd < 4; nd++) {
                O[mi][nd][0] *= c0; O[mi][nd][1] *= c0;
                O[mi][nd][2] *= c1; O[mi][nd][3] *= c1;
            }
#pragma unroll
            for (int kg = 0; kg < 2; kg++) {
                Ph[mi][kg][0] = pack_hi(sc[mi][2 * kg][0],     sc[mi][2 * kg][1]);
                Ph[mi][kg][1] = pack_hi(sc[mi][2 * kg][2],     sc[mi][2 * kg][3]);
                Ph[mi][kg][2] = pack_hi(sc[mi][2 * kg + 1][0], sc[mi][2 * kg + 1][1]);
                Ph[mi][kg][3] = pack_hi(sc[mi][2 * kg + 1][2], sc[mi][2 * kg + 1][3]);
                Pl[mi][kg][0] = pack_lo(sc[mi][2 * kg][0],     sc[mi][2 * kg][1]);
                Pl[mi][kg][1] = pack_lo(sc[mi][2 * kg][2],     sc[mi][2 * kg][3]);
                Pl[mi][kg][2] = pack_lo(sc[mi][2 * kg + 1][0], sc[mi][2 * kg + 1][1]);
                Pl[mi][kg][3] = pack_lo(sc[mi][2 * kg + 1][2], sc[mi][2 * kg + 1][3]);
            }
        }

        // PV: 2 MMAs (V lo dropped)
#pragma unroll
        for (int kg = 0; kg < 2; kg++)
#pragma unroll
            for (int nd = 0; nd < 4; nd++) {
                uint32_t vh0, vh1;
                uint32_t ad = sbase + A_VH + (nd * 8 + krow) * 1040 + (kb + kg * 16) * 2 + ksel;
                LDMX2(vh0, vh1, ad);
#pragma unroll
                for (int mi = 0; mi < 4; mi++) {
                    MMA16816(O[mi][nd], Ph[mi][kg], vh0, vh1);
                    MMA16816(O[mi][nd], Pl[mi][kg], vh0, vh1);
                }
            }
    }

    int r0 = wid * 64;
#pragma unroll
    for (int mi = 0; mi < 4; mi++) {
        float li0 = 1.f / lr[2 * mi], li1 = 1.f / lr[2 * mi + 1];
        int grow = b * NSEQ + r0 + mi * 16 + (lane >> 2);
#pragma unroll
        for (int nd = 0; nd < 4; nd++) {
            int col = h * DH + nd * 8 + (lane & 3) * 2;
            float v0 = O[mi][nd][0] * li0, v1 = O[mi][nd][1] * li0;
            float v2 = O[mi][nd][2] * li1, v3 = O[mi][nd][3] * li1;
            __nv_bfloat162 h0, l0, h1, l1;
            split_pair(v0, v1, h0, l0);
            split_pair(v2, v3, h1, l1);
            *(__nv_bfloat162*)(aoh + (size_t)grow * C + col)       = h0;
            *(__nv_bfloat162*)(aol + (size_t)grow * C + col)       = l0;
            *(__nv_bfloat162*)(aoh + (size_t)(grow + 8) * C + col) = h1;
            *(__nv_bfloat162*)(aol + (size_t)(grow + 8) * C + col) = l1;
        }
    }
}

// ================= BN coef / apply =================
__global__ void bn_coef(const float* __restrict__ stats, const float* __restrict__ g,
                        const float* __restrict__ b, float* __restrict__ coef) {
    int c = threadIdx.x;
    float m = stats[c] * (1.0f / NT);
    float v = stats[C + c] * (1.0f / NT) - m * m;
    float a = g[c] * rsqrtf(v + EPS);
    coef[c] = a;
    coef[C + c] = b[c] - m * a;
}

__global__ void apply_kernel(const float* __restrict__ src, const float* __restrict__ coef,
                             float* __restrict__ out) {
    int i = blockIdx.x * blockDim.x + threadIdx.x;
    int c4 = (i & 31) * 4;
    float4 a = *(const float4*)(coef + c4);
    float4 c = *(const float4*)(coef + C + c4);
    float4 u = ((const float4*)src)[i];
    float4 r;
    r.x = fmaf(u.x, a.x, c.x);
    r.y = fmaf(u.y, a.y, c.y);
    r.z = fmaf(u.z, a.z, c.z);
    r.w = fmaf(u.w, a.w, c.w);
    ((float4*)out)[i] = r;
}

// ================= launch =================
extern "C" void kernel_launch(void* const* d_in, const int* in_sizes, int n_in,
                              void* d_out, int out_size) {
    const float* x    = (const float*)d_in[0];
    const int*   ei   = (const int*)  d_in[1];
    const float* Wc   = (const float*)d_in[2];
    const float* bc   = (const float*)d_in[3];
    const float* inw  = (const float*)d_in[4];
    const float* inb  = (const float*)d_in[5];
    const float* outw = (const float*)d_in[6];
    const float* outb = (const float*)d_in[7];
    const float* gn1  = (const float*)d_in[8];
    const float* bn1  = (const float*)d_in[9];
    const float* gn2  = (const float*)d_in[10];
    const float* bn2  = (const float*)d_in[11];
    const float* gn3  = (const float*)d_in[12];
    const float* bn3  = (const float*)d_in[13];
    const float* Wm1  = (const float*)d_in[14];
    const float* bm1  = (const float*)d_in[15];
    const float* Wm2  = (const float*)d_in[16];
    const float* bm2  = (const float*)d_in[17];
    float* out = (float*)d_out;

    float *agg, *cnt, *hl, *ha, *cmb, *tb, *stats, *coef, *inbs;
    __nv_bfloat16 *xh, *xl, *agh, *agl, *qkvh, *qkvl, *aoh, *aol, *m1h, *m1l;
    __nv_bfloat16 *wch, *wcl, *wih, *wil, *woh, *wol, *w1h, *w1l, *w2h, *w2l;
    cudaGetSymbolAddress((void**)&agg, g_agg);   cudaGetSymbolAddress((void**)&cnt, g_cnt);
    cudaGetSymbolAddress((void**)&hl, g_hl);     cudaGetSymbolAddress((void**)&ha, g_ha);
    cudaGetSymbolAddress((void**)&cmb, g_cmb);   cudaGetSymbolAddress((void**)&tb, g_tb);
    cudaGetSymbolAddress((void**)&stats, g_stats); cudaGetSymbolAddress((void**)&coef, g_coef);
    cudaGetSymbolAddress((void**)&inbs, g_inbs);
    cudaGetSymbolAddress((void**)&xh, g_x_h);    cudaGetSymbolAddress((void**)&xl, g_x_l);
    cudaGetSymbolAddress((void**)&agh, g_ag_h);  cudaGetSymbolAddress((void**)&agl, g_ag_l);
    cudaGetSymbolAddress((void**)&qkvh, g_qkvh); cudaGetSymbolAddress((void**)&qkvl, g_qkvl);
    cudaGetSymbolAddress((void**)&aoh, g_ao_h);  cudaGetSymbolAddress((void**)&aol, g_ao_l);
    cudaGetSymbolAddress((void**)&m1h, g_m1_h);  cudaGetSymbolAddress((void**)&m1l, g_m1_l);
    cudaGetSymbolAddress((void**)&wch, g_wc_h);  cudaGetSymbolAddress((void**)&wcl, g_wc_l);
    cudaGetSymbolAddress((void**)&wih, g_wi_h);  cudaGetSymbolAddress((void**)&wil, g_wi_l);
    cudaGetSymbolAddress((void**)&woh, g_wo_h);  cudaGetSymbolAddress((void**)&wol, g_wo_l);
    cudaGetSymbolAddress((void**)&w1h, g_w1_h);  cudaGetSymbolAddress((void**)&w1l, g_w1_l);
    cudaGetSymbolAddress((void**)&w2h, g_w2_h);  cudaGetSymbolAddress((void**)&w2l, g_w2_l);

    cudaFuncSetAttribute(gemm_mma, cudaFuncAttributeMaxDynamicSharedMemorySize, GEMM_SMEM);
    cudaFuncSetAttribute(attn_mma, cudaFuncAttributeMaxDynamicSharedMemorySize, ATTN_SMEM);

    cudaMemsetAsync(agg, 0, sizeof(float) * NT * C);
    cudaMemsetAsync(cnt, 0, sizeof(float) * NT);
    cudaMemsetAsync(stats, 0, sizeof(float) * 6 * C);

    // conversions
    conv_split<<<NT * C / 4 / 256, 256>>>(x, xh, xl, NT * C / 4);
    conv_weights<<<145, 256>>>(Wc, inw, outw, Wm1, Wm2, inb,
                               wch, wcl, wih, wil, woh, wol, w1h, w1l, w2h, w2l, inbs);

    // local branch
    scatter_kernel<<<NEDGE / 8, 256>>>(x, ei, agg, cnt);
    conv_agg<<<NT * C / 4 / 256, 256>>>(agg, cnt, agh, agl);
    gemm_mma<<<dim3(NT / 128, 1), 256, GEMM_SMEM>>>(agh, agl, wch, wcl, bc, x,
        hl, nullptr, nullptr, stats, nullptr, nullptr, nullptr, nullptr, 128, 128, 0);

    // global branch (qkv in bf16 hi/lo; Q scale folded into weights)
    gemm_mma<<<dim3(NT / 128, 3), 256, GEMM_SMEM>>>(xh, xl, wih, wil, inbs, nullptr,
        nullptr, qkvh, qkvl, nullptr, nullptr, nullptr, nullptr, nullptr, 128, 384, 0);
    attn_mma<<<BATCH * H, 256, ATTN_SMEM>>>(qkvh, qkvl, aoh, aol);
    gemm_mma<<<dim3(NT / 128, 1), 256, GEMM_SMEM>>>(aoh, aol, woh, wol, outb, x,
        ha, nullptr, nullptr, stats + 2 * C, nullptr, nullptr, nullptr, nullptr, 128, 128, 0);

    // BN coefs, then MLP with fused combine
    bn_coef<<<1, 128>>>(stats, gn1, bn1, coef);
    bn_coef<<<1, 128>>>(stats + 2 * C, gn2, bn2, coef + 2 * C);
    gemm_mma<<<dim3(NT / 128, 2), 256, GEMM_SMEM>>>(nullptr, nullptr, w1h, w1l, bm1, nullptr,
        nullptr, m1h, m1l, nullptr, hl, ha, coef, cmb, 128, 256, 1);
    gemm_mma<<<dim3(NT / 128, 1), 256, GEMM_SMEM>>>(m1h, m1l, w2h, w2l, bm2, cmb,
        tb, nullptr, nullptr, stats + 4 * C, nullptr, nullptr, nullptr, nullptr, 256, 128, 0);

    // final BN
    bn_coef<<<1, 128>>>(stats + 4 * C, gn3, bn3, coef + 4 * C);
    apply_kernel<<<NT * C / 4 / 256, 256>>>(tb, coef + 4 * C, out);
}